// round 9
// baseline (speedup 1.0000x reference)
#include <cuda_runtime.h>
#include <cuda_bf16.h>
#include <math.h>
#include <stdint.h>

// ---------------- problem constants ----------------
constexpr int Bc   = 2;
constexpr int Sc   = 2048;
constexpr int HID  = 2048;
constexpr int Hc   = 16;
constexpr int KVc  = 4;
constexpr int Dc   = 128;
constexpr int Mc   = Bc * Sc;         // 4096
constexpr int NQ   = 2 * Hc * Dc;     // 4096 (q | gate)
constexpr int NK   = KVc * Dc;        // 512
constexpr float ATT_SCALE = 0.08838834764831845f;   // 1/sqrt(128)
constexpr float LOG2E = 1.4426950408889634f;

// ---------------- scratch (device globals; no allocations allowed) ----------------
__device__ float g_qraw[(size_t)Mc * NQ];
__device__ float g_k   [(size_t)Mc * NK];

__device__ __nv_bfloat16 g_xh[(size_t)Mc * HID];
__device__ __nv_bfloat16 g_xl[(size_t)Mc * HID];
__device__ __nv_bfloat16 g_zh[(size_t)Mc * HID];
__device__ __nv_bfloat16 g_zl[(size_t)Mc * HID];
__device__ __nv_bfloat16 g_wqh[(size_t)NQ * HID];
__device__ __nv_bfloat16 g_wql[(size_t)NQ * HID];
__device__ __nv_bfloat16 g_wkh[(size_t)NK * HID];
__device__ __nv_bfloat16 g_wkl[(size_t)NK * HID];
__device__ __nv_bfloat16 g_wvh[(size_t)NK * HID];
__device__ __nv_bfloat16 g_wvl[(size_t)NK * HID];
__device__ __nv_bfloat16 g_woh[(size_t)HID * HID];
__device__ __nv_bfloat16 g_wol[(size_t)HID * HID];

__device__ __nv_bfloat16 g_qbh[(size_t)Mc * Hc * Dc];
__device__ __nv_bfloat16 g_qbl[(size_t)Mc * Hc * Dc];
__device__ __nv_bfloat16 g_kbh[(size_t)Mc * NK];
__device__ __nv_bfloat16 g_kbl[(size_t)Mc * NK];
__device__ __nv_bfloat16 g_vbh[(size_t)Mc * NK];
__device__ __nv_bfloat16 g_vbl[(size_t)Mc * NK];

// ---------------- baseline-PTX helpers ----------------
__device__ __forceinline__ uint32_t smem_u32(const void* p) {
    return (uint32_t)__cvta_generic_to_shared(p);
}
__device__ __forceinline__ void cp_async16(uint32_t dst, const void* src) {
    asm volatile("cp.async.cg.shared.global [%0], [%1], 16;" :: "r"(dst), "l"(src));
}
__device__ __forceinline__ void cp_commit() {
    asm volatile("cp.async.commit_group;" ::: "memory");
}
__device__ __forceinline__ void cp_wait1() {
    asm volatile("cp.async.wait_group 1;" ::: "memory");
}
__device__ __forceinline__ void cp_wait0() {
    asm volatile("cp.async.wait_group 0;" ::: "memory");
}
__device__ __forceinline__ void ldm_x4(uint32_t& r0, uint32_t& r1, uint32_t& r2, uint32_t& r3,
                                       uint32_t addr) {
    asm volatile("ldmatrix.sync.aligned.m8n8.x4.shared.b16 {%0,%1,%2,%3}, [%4];"
                 : "=r"(r0), "=r"(r1), "=r"(r2), "=r"(r3) : "r"(addr));
}
__device__ __forceinline__ void ldm_x4_t(uint32_t& r0, uint32_t& r1, uint32_t& r2, uint32_t& r3,
                                         uint32_t addr) {
    asm volatile("ldmatrix.sync.aligned.m8n8.x4.trans.shared.b16 {%0,%1,%2,%3}, [%4];"
                 : "=r"(r0), "=r"(r1), "=r"(r2), "=r"(r3) : "r"(addr));
}
__device__ __forceinline__ void mma_bf16(float* c, const uint32_t* a, uint32_t b0, uint32_t b1) {
    asm volatile(
        "mma.sync.aligned.m16n8k16.row.col.f32.bf16.bf16.f32 "
        "{%0,%1,%2,%3}, {%4,%5,%6,%7}, {%8,%9}, {%0,%1,%2,%3};"
        : "+f"(c[0]), "+f"(c[1]), "+f"(c[2]), "+f"(c[3])
        : "r"(a[0]), "r"(a[1]), "r"(a[2]), "r"(a[3]), "r"(b0), "r"(b1));
}
__device__ __forceinline__ float ex2f(float x) {
    float y; asm("ex2.approx.f32 %0, %1;" : "=f"(y) : "f"(x)); return y;
}
__device__ __forceinline__ void bf_split(float v, __nv_bfloat16& h, __nv_bfloat16& l) {
    h = __float2bfloat16(v);
    l = __float2bfloat16(v - __bfloat162float(h));
}
__device__ __forceinline__ void cvt_split2(float p0, float p1, uint32_t& hi, uint32_t& lo) {
    __nv_bfloat162 h = __floats2bfloat162_rn(p0, p1);
    __nv_bfloat162 l = __floats2bfloat162_rn(p0 - __bfloat162float(h.x),
                                             p1 - __bfloat162float(h.y));
    hi = *reinterpret_cast<uint32_t*>(&h);
    lo = *reinterpret_cast<uint32_t*>(&l);
}
__device__ __forceinline__ unsigned short us(__nv_bfloat16 v) {
    return __bfloat16_as_ushort(v);
}

// ====================================================================
// HMMA split-bf16 GEMM, single-pass 3-term, 128(M) x 256(N) CTA tile.
// BK=32, 2-stage cp.async double buffer, 8 warps (4M x 2N), warp tile
// 32x128. acc = 128 regs/thread; 1 CTA/SM. Optional second (B,C) set
// selected by blockIdx.x >= nsplit; mode2 writes bf16 hi/lo split.
// ====================================================================
constexpr int LDT = 40;                        // padded row length (elements)
constexpr int AT_B = 128 * LDT * 2;            // 10240 B per A operand tile
constexpr int BT_B = 256 * LDT * 2;            // 20480 B per B operand tile
constexpr int STAGE_B = 2 * AT_B + 2 * BT_B;   // 61440 B (Ah,Al,Bh,Bl)
constexpr int HG_SMEM = 2 * STAGE_B;           // 122880 B

__global__ __launch_bounds__(256, 1)
void hgemm_split(const __nv_bfloat16* __restrict__ Ah, const __nv_bfloat16* __restrict__ Al,
                 const __nv_bfloat16* __restrict__ Bh, const __nv_bfloat16* __restrict__ Bl,
                 float* __restrict__ C,
                 const __nv_bfloat16* __restrict__ Bh2, const __nv_bfloat16* __restrict__ Bl2,
                 float* __restrict__ C2,
                 __nv_bfloat16* __restrict__ C2h, __nv_bfloat16* __restrict__ C2l,
                 int mode2, int nsplit,
                 int M, int N, int K)
{
    extern __shared__ __align__(128) char smem[];
    const uint32_t sb = smem_u32(smem);

    const int tid  = threadIdx.x;
    const int warp = tid >> 5, lane = tid & 31;

    const __nv_bfloat16* Bh_ = Bh;
    const __nv_bfloat16* Bl_ = Bl;
    int bx = blockIdx.x;
    bool use2 = false;
    if (bx >= nsplit) { Bh_ = Bh2; Bl_ = Bl2; use2 = true; bx -= nsplit; }
    const int n0 = bx * 256;
    const int m0 = blockIdx.y * 128;
    const int wm = (warp >> 1) * 32;      // 4 M-warps
    const int wn = (warp & 1) * 128;      // 2 N-warps

    const int KT = K / 32;

    const int lrow = tid >> 2;            // 0..63
    const int lcc  = tid & 3;             // 16B chunk in 64B k-row

    auto issue_stage = [&](int kt) {
        const uint32_t stg = sb + (kt & 1) * STAGE_B;
        const uint32_t soff = (lrow * LDT + lcc * 8) * 2;
        const size_t koff = (size_t)kt * 32 + lcc * 8;
        const __nv_bfloat16* pah = Ah  + (size_t)(m0 + lrow) * K + koff;
        const __nv_bfloat16* pal = Al  + (size_t)(m0 + lrow) * K + koff;
        const __nv_bfloat16* pbh = Bh_ + (size_t)(n0 + lrow) * K + koff;
        const __nv_bfloat16* pbl = Bl_ + (size_t)(n0 + lrow) * K + koff;
        const uint32_t rstep = 64 * LDT * 2;
        // A: rows lrow, lrow+64
        cp_async16(stg + soff,                pah);
        cp_async16(stg + soff + rstep,        pah + (size_t)64 * K);
        cp_async16(stg + AT_B + soff,         pal);
        cp_async16(stg + AT_B + soff + rstep, pal + (size_t)64 * K);
        // B: rows lrow, +64, +128, +192
        const uint32_t bb = stg + 2 * AT_B;
        #pragma unroll
        for (int r = 0; r < 4; r++) {
            cp_async16(bb + soff + r * rstep,        pbh + (size_t)(64 * r) * K);
            cp_async16(bb + BT_B + soff + r * rstep, pbl + (size_t)(64 * r) * K);
        }
    };

    float acc[2][16][4];
    #pragma unroll
    for (int i = 0; i < 2; i++)
        #pragma unroll
        for (int j = 0; j < 16; j++)
            #pragma unroll
            for (int q = 0; q < 4; q++) acc[i][j][q] = 0.f;

    const int a_row = lane & 15;
    const int a_ko  = (lane >> 4) << 3;
    const int b_row = ((lane >> 4) << 3) + (lane & 7);
    const int b_ko  = ((lane >> 3) & 1) << 3;

    issue_stage(0); cp_commit();

    for (int kt = 0; kt < KT; kt++) {
        if (kt + 1 < KT) { issue_stage(kt + 1); cp_commit(); cp_wait1(); }
        else             { cp_wait0(); }
        __syncthreads();

        const uint32_t sa_h = sb + (kt & 1) * STAGE_B;
        const uint32_t sa_l = sa_h + AT_B;
        const uint32_t sb_h = sa_h + 2 * AT_B;
        const uint32_t sb_l = sb_h + BT_B;

        #pragma unroll
        for (int ks = 0; ks < 32; ks += 16) {
            uint32_t ah[2][4], al[2][4];
            #pragma unroll
            for (int mi = 0; mi < 2; mi++) {
                uint32_t off = ((wm + mi * 16 + a_row) * LDT + ks + a_ko) * 2;
                ldm_x4(ah[mi][0], ah[mi][1], ah[mi][2], ah[mi][3], sa_h + off);
                ldm_x4(al[mi][0], al[mi][1], al[mi][2], al[mi][3], sa_l + off);
            }
            #pragma unroll
            for (int nb = 0; nb < 8; nb++) {
                uint32_t bh[4], bl[4];
                uint32_t off = ((wn + nb * 16 + b_row) * LDT + ks + b_ko) * 2;
                ldm_x4(bh[0], bh[1], bh[2], bh[3], sb_h + off);
                ldm_x4(bl[0], bl[1], bl[2], bl[3], sb_l + off);
                #pragma unroll
                for (int mi = 0; mi < 2; mi++) {
                    mma_bf16(acc[mi][2 * nb],     ah[mi], bh[0], bh[1]);
                    mma_bf16(acc[mi][2 * nb + 1], ah[mi], bh[2], bh[3]);
                    mma_bf16(acc[mi][2 * nb],     ah[mi], bl[0], bl[1]);
                    mma_bf16(acc[mi][2 * nb + 1], ah[mi], bl[2], bl[3]);
                    mma_bf16(acc[mi][2 * nb],     al[mi], bh[0], bh[1]);
                    mma_bf16(acc[mi][2 * nb + 1], al[mi], bh[2], bh[3]);
                }
            }
        }
        __syncthreads();
    }

    if (use2 && mode2) {
        #pragma unroll
        for (int mi = 0; mi < 2; mi++) {
            const int r0 = m0 + wm + mi * 16 + (lane >> 2);
            #pragma unroll
            for (int ni = 0; ni < 16; ni++) {
                const int col = n0 + wn + ni * 8 + 2 * (lane & 3);
                __nv_bfloat16 h0, l0, h1, l1, h2, l2, h3, l3;
                bf_split(acc[mi][ni][0], h0, l0);
                bf_split(acc[mi][ni][1], h1, l1);
                bf_split(acc[mi][ni][2], h2, l2);
                bf_split(acc[mi][ni][3], h3, l3);
                *(ushort2*)&C2h[(size_t)r0 * N + col]       = make_ushort2(us(h0), us(h1));
                *(ushort2*)&C2l[(size_t)r0 * N + col]       = make_ushort2(us(l0), us(l1));
                *(ushort2*)&C2h[(size_t)(r0 + 8) * N + col] = make_ushort2(us(h2), us(h3));
                *(ushort2*)&C2l[(size_t)(r0 + 8) * N + col] = make_ushort2(us(l2), us(l3));
            }
        }
    } else {
        float* C_ = use2 ? C2 : C;
        #pragma unroll
        for (int mi = 0; mi < 2; mi++) {
            const int r0 = m0 + wm + mi * 16 + (lane >> 2);
            #pragma unroll
            for (int ni = 0; ni < 16; ni++) {
                const int col = n0 + wn + ni * 8 + 2 * (lane & 3);
                *(float2*)&C_[(size_t)r0 * N + col]       = make_float2(acc[mi][ni][0], acc[mi][ni][1]);
                *(float2*)&C_[(size_t)(r0 + 8) * N + col] = make_float2(acc[mi][ni][2], acc[mi][ni][3]);
            }
        }
    }
}

// ====================================================================
// fp32 -> bf16 hi/lo split (elementwise)
// ====================================================================
__global__ __launch_bounds__(256) void split_f32(const float* __restrict__ in,
                                                 __nv_bfloat16* __restrict__ hi,
                                                 __nv_bfloat16* __restrict__ lo, int n4)
{
    int i = blockIdx.x * 256 + threadIdx.x;
    if (i >= n4) return;
    float4 v = ((const float4*)in)[i];
    __nv_bfloat16 h0, h1, h2, h3, l0, l1, l2, l3;
    bf_split(v.x, h0, l0); bf_split(v.y, h1, l1);
    bf_split(v.z, h2, l2); bf_split(v.w, h3, l3);
    ((ushort4*)hi)[i] = make_ushort4(us(h0), us(h1), us(h2), us(h3));
    ((ushort4*)lo)[i] = make_ushort4(us(l0), us(l1), us(l2), us(l3));
}

// ====================================================================
// fp32 [R,C] -> transposed bf16 hi/lo [C,R]
// ====================================================================
__global__ __launch_bounds__(256) void transpose_split(const float* __restrict__ in,
                                                       __nv_bfloat16* __restrict__ hiT,
                                                       __nv_bfloat16* __restrict__ loT,
                                                       int R, int C)
{
    __shared__ float t[32][33];
    int c0 = blockIdx.x * 32, r0 = blockIdx.y * 32;
    int tx = threadIdx.x, ty = threadIdx.y;
    #pragma unroll
    for (int k = 0; k < 4; k++)
        t[ty + 8 * k][tx] = in[(size_t)(r0 + ty + 8 * k) * C + c0 + tx];
    __syncthreads();
    #pragma unroll
    for (int k = 0; k < 4; k++) {
        float v = t[tx][ty + 8 * k];
        __nv_bfloat16 h, l;
        bf_split(v, h, l);
        size_t o = (size_t)(c0 + ty + 8 * k) * R + r0 + tx;
        hiT[o] = h;
        loT[o] = l;
    }
}

// ====================================================================
// RMSNorm + RoPE -> bf16 hi/lo
// ====================================================================
__device__ __forceinline__ void norm_rope_bf(const float* __restrict__ src,
                                             __nv_bfloat16* __restrict__ dh,
                                             __nv_bfloat16* __restrict__ dl,
                                             const float* __restrict__ w,
                                             int pos, int lane, float outscale)
{
    float x0 = src[lane], x1 = src[lane + 32], x2 = src[lane + 64], x3 = src[lane + 96];
    float ss = x0 * x0 + x1 * x1 + x2 * x2 + x3 * x3;
    #pragma unroll
    for (int o = 16; o; o >>= 1) ss += __shfl_xor_sync(0xffffffffu, ss, o);
    float rn = rsqrtf(ss * (1.0f / 128.0f) + 1e-6f);
    float y0 = x0 * rn * (w[lane] + 1.f);
    float y1 = x1 * rn * (w[lane + 32] + 1.f);
    float y2 = x2 * rn * (w[lane + 64] + 1.f);
    float y3 = x3 * rn * (w[lane + 96] + 1.f);
    float inv0 = powf(1000000.0f, -(float)(2 * lane) / 128.f);
    float inv1 = powf(1000000.0f, -(float)(2 * (lane + 32)) / 128.f);
    float f0 = (float)pos * inv0, f1 = (float)pos * inv1;
    float c0, s0, c1, s1;
    sincosf(f0, &s0, &c0);
    sincosf(f1, &s1, &c1);
    float o0  = (y0 * c0 - y2 * s0) * outscale;
    float o64 = (y2 * c0 + y0 * s0) * outscale;
    float o32 = (y1 * c1 - y3 * s1) * outscale;
    float o96 = (y3 * c1 + y1 * s1) * outscale;
    __nv_bfloat16 h, l;
    bf_split(o0, h, l);  dh[lane]      = h; dl[lane]      = l;
    bf_split(o64, h, l); dh[lane + 64] = h; dl[lane + 64] = l;
    bf_split(o32, h, l); dh[lane + 32] = h; dl[lane + 32] = l;
    bf_split(o96, h, l); dh[lane + 96] = h; dl[lane + 96] = l;
}

__global__ __launch_bounds__(256) void norm_rope_q_bf(const float* __restrict__ qraw,
                                                      const float* __restrict__ w,
                                                      __nv_bfloat16* __restrict__ qh,
                                                      __nv_bfloat16* __restrict__ ql)
{
    int warp = blockIdx.x * 8 + (threadIdx.x >> 5);
    int lane = threadIdx.x & 31;
    if (warp >= Mc * Hc) return;
    int m = warp >> 4;
    int h = warp & 15;
    int pos = m & (Sc - 1);
    const float* src = qraw + (size_t)m * NQ + h * (2 * Dc);
    size_t dof = (size_t)m * (Hc * Dc) + h * Dc;
    norm_rope_bf(src, qh + dof, ql + dof, w, pos, lane, ATT_SCALE);
}

__global__ __launch_bounds__(256) void norm_rope_k_bf(const float* __restrict__ kraw,
                                                      const float* __restrict__ w,
                                                      __nv_bfloat16* __restrict__ kh,
                                                      __nv_bfloat16* __restrict__ kl)
{
    int warp = blockIdx.x * 8 + (threadIdx.x >> 5);
    int lane = threadIdx.x & 31;
    if (warp >= Mc * KVc) return;
    int m = warp >> 2;
    int pos = m & (Sc - 1);
    const float* src = kraw + (size_t)warp * Dc;
    norm_rope_bf(src, kh + (size_t)warp * Dc, kl + (size_t)warp * Dc, w, pos, lane, 1.0f);
}

// ====================================================================
// HMMA flash attention (BQ=128, BK=64, 2-stage ring)
// + fused sigmoid gate + bf16-split z output.
// ====================================================================
constexpr int ALD = 136;
constexpr int Q_ELE = 128 * ALD;
constexpr int KV_TILE_E = 64 * ALD;
constexpr int KV_STAGE_E = 4 * KV_TILE_E;
constexpr int SM_KV_E = 2 * Q_ELE;
constexpr int ATTN_SMEM = (2 * Q_ELE + 2 * KV_STAGE_E) * 2;

__global__ __launch_bounds__(256, 1)
void attn_mma(const __nv_bfloat16* __restrict__ qh, const __nv_bfloat16* __restrict__ ql,
              const __nv_bfloat16* __restrict__ kh, const __nv_bfloat16* __restrict__ kl,
              const __nv_bfloat16* __restrict__ vh, const __nv_bfloat16* __restrict__ vl,
              const float* __restrict__ qraw,
              __nv_bfloat16* __restrict__ Zh, __nv_bfloat16* __restrict__ Zl)
{
    extern __shared__ __align__(128) char smem[];
    const uint32_t sb = smem_u32(smem);

    const int tid = threadIdx.x;
    const int warp = tid >> 5, lane = tid & 31;
    const int qt = (int)gridDim.x - 1 - (int)blockIdx.x;
    const int h  = blockIdx.y;
    const int b  = blockIdx.z;
    const int kv = h >> 2;
    const int q0 = qt * 128;
    const int wm = warp * 16;
    const size_t bS = (size_t)b * Sc;
    const int KT = 2 * qt + 2;

    const int a_row = lane & 15;
    const int a_ko  = (lane >> 4) << 3;
    const int b_row = ((lane >> 4) << 3) + (lane & 7);
    const int b_ko  = ((lane >> 3) & 1) << 3;
    const int v_row = (lane & 7) + (((lane >> 3) & 1) << 3);
    const int v_co  = (lane >> 4) << 3;

    auto issue_kv = [&](int kt) {
        const uint32_t stg = sb + (SM_KV_E + (kt & 1) * KV_STAGE_E) * 2;
        #pragma unroll
        for (int p = 0; p < 4; p++) {
            int cid = tid + 256 * p;
            int row = cid >> 4, ch = cid & 15;
            size_t go = (bS + kt * 64 + row) * NK + kv * Dc + ch * 8;
            uint32_t so = (row * ALD + ch * 8) * 2;
            cp_async16(stg + so,                     kh + go);
            cp_async16(stg + KV_TILE_E * 2 + so,     kl + go);
            cp_async16(stg + 2 * KV_TILE_E * 2 + so, vh + go);
            cp_async16(stg + 3 * KV_TILE_E * 2 + so, vl + go);
        }
    };

    #pragma unroll
    for (int p = 0; p < 8; p++) {
        int cid = tid + 256 * p;
        int row = cid >> 4, ch = cid & 15;
        size_t go = (bS + q0 + row) * ((size_t)Hc * Dc) + h * Dc + ch * 8;
        uint32_t so = (row * ALD + ch * 8) * 2;
        cp_async16(sb + so,             qh + go);
        cp_async16(sb + Q_ELE * 2 + so, ql + go);
    }
    issue_kv(0);
    cp_commit();
    if (KT > 1) issue_kv(1);
    cp_commit();

    float oacc[16][4];
    #pragma unroll
    for (int t = 0; t < 16; t++)
        #pragma unroll
        for (int q = 0; q < 4; q++) oacc[t][q] = 0.f;
    float m1 = -1e30f, m2 = -1e30f, l1 = 0.f, l2 = 0.f;

    for (int kt = 0; kt < KT; kt++) {
        cp_wait1();
        __syncthreads();

        const bool wskip = (kt * 64) > (q0 + wm + 15);
        if (!wskip) {
            const uint32_t stg = sb + (SM_KV_E + (kt & 1) * KV_STAGE_E) * 2;
            const uint32_t sK_h = stg;
            const uint32_t sK_l = stg + KV_TILE_E * 2;
            const uint32_t sV_h = stg + 2 * KV_TILE_E * 2;
            const uint32_t sV_l = stg + 3 * KV_TILE_E * 2;

            float sacc[8][4];
            #pragma unroll
            for (int f = 0; f < 8; f++)
                #pragma unroll
                for (int q = 0; q < 4; q++) sacc[f][q] = 0.f;

            #pragma unroll
            for (int ks = 0; ks < 8; ks++) {
                uint32_t ah[4], al[4];
                uint32_t qaddr = sb + ((wm + a_row) * ALD + ks * 16 + a_ko) * 2;
                ldm_x4(ah[0], ah[1], ah[2], ah[3], qaddr);
                ldm_x4(al[0], al[1], al[2], al[3], qaddr + Q_ELE * 2);
                #pragma unroll
                for (int nb = 0; nb < 4; nb++) {
                    uint32_t bh[4], bl[4];
                    uint32_t kaddr = ((nb * 16 + b_row) * ALD + ks * 16 + b_ko) * 2;
                    ldm_x4(bh[0], bh[1], bh[2], bh[3], sK_h + kaddr);
                    ldm_x4(bl[0], bl[1], bl[2], bl[3], sK_l + kaddr);
                    mma_bf16(sacc[2 * nb],     ah, bh[0], bh[1]);
                    mma_bf16(sacc[2 * nb + 1], ah, bh[2], bh[3]);
                    mma_bf16(sacc[2 * nb],     ah, bl[0], bl[1]);
                    mma_bf16(sacc[2 * nb + 1], ah, bl[2], bl[3]);
                    mma_bf16(sacc[2 * nb],     al, bh[0], bh[1]);
                    mma_bf16(sacc[2 * nb + 1], al, bh[2], bh[3]);
                }
            }

            const int r1 = q0 + wm + (lane >> 2);
            const int r2 = r1 + 8;
            if (kt * 64 + 63 > q0 + wm) {
                #pragma unroll
                for (int f = 0; f < 8; f++) {
                    int cb = kt * 64 + 8 * f + 2 * (lane & 3);
                    if (cb     > r1) sacc[f][0] = -1e30f;
                    if (cb + 1 > r1) sacc[f][1] = -1e30f;
                    if (cb     > r2) sacc[f][2] = -1e30f;
                    if (cb + 1 > r2) sacc[f][3] = -1e30f;
                }
            }

            float mx1 = -1e30f, mx2 = -1e30f;
            #pragma unroll
            for (int f = 0; f < 8; f++) {
                mx1 = fmaxf(mx1, fmaxf(sacc[f][0], sacc[f][1]));
                mx2 = fmaxf(mx2, fmaxf(sacc[f][2], sacc[f][3]));
            }
            mx1 = fmaxf(mx1, __shfl_xor_sync(0xffffffffu, mx1, 1));
            mx1 = fmaxf(mx1, __shfl_xor_sync(0xffffffffu, mx1, 2));
            mx2 = fmaxf(mx2, __shfl_xor_sync(0xffffffffu, mx2, 1));
            mx2 = fmaxf(mx2, __shfl_xor_sync(0xffffffffu, mx2, 2));
            float m1n = fmaxf(m1, mx1), m2n = fmaxf(m2, mx2);
            float al1 = ex2f((m1 - m1n) * LOG2E);
            float al2 = ex2f((m2 - m2n) * LOG2E);
            m1 = m1n; m2 = m2n;

            float rs1 = 0.f, rs2 = 0.f;
            #pragma unroll
            for (int f = 0; f < 8; f++) {
                sacc[f][0] = ex2f((sacc[f][0] - m1n) * LOG2E);
                sacc[f][1] = ex2f((sacc[f][1] - m1n) * LOG2E);
                sacc[f][2] = ex2f((sacc[f][2] - m2n) * LOG2E);
                sacc[f][3] = ex2f((sacc[f][3] - m2n) * LOG2E);
                rs1 += sacc[f][0] + sacc[f][1];
                rs2 += sacc[f][2] + sacc[f][3];
            }
            rs1 += __shfl_xor_sync(0xffffffffu, rs1, 1);
            rs1 += __shfl_xor_sync(0xffffffffu, rs1, 2);
            rs2 += __shfl_xor_sync(0xffffffffu, rs2, 1);
            rs2 += __shfl_xor_sync(0xffffffffu, rs2, 2);
            l1 = l1 * al1 + rs1;
            l2 = l2 * al2 + rs2;

            #pragma unroll
            for (int t = 0; t < 16; t++) {
                oacc[t][0] *= al1; oacc[t][1] *= al1;
                oacc[t][2] *= al2; oacc[t][3] *= al2;
            }

            #pragma unroll
            for (int j = 0; j < 4; j++) {
                uint32_t pah[4], pal[4];
                cvt_split2(sacc[2 * j][0],     sacc[2 * j][1],     pah[0], pal[0]);
                cvt_split2(sacc[2 * j][2],     sacc[2 * j][3],     pah[1], pal[1]);
                cvt_split2(sacc[2 * j + 1][0], sacc[2 * j + 1][1], pah[2], pal[2]);
                cvt_split2(sacc[2 * j + 1][2], sacc[2 * j + 1][3], pah[3], pal[3]);
                #pragma unroll
                for (int db = 0; db < 8; db++) {
                    uint32_t bh[4], bl[4];
                    uint32_t vaddr = ((j * 16 + v_row) * ALD + db * 16 + v_co) * 2;
                    ldm_x4_t(bh[0], bh[1], bh[2], bh[3], sV_h + vaddr);
                    ldm_x4_t(bl[0], bl[1], bl[2], bl[3], sV_l + vaddr);
                    mma_bf16(oacc[2 * db],     pah, bh[0], bh[1]);
                    mma_bf16(oacc[2 * db + 1], pah, bh[2], bh[3]);
                    mma_bf16(oacc[2 * db],     pah, bl[0], bl[1]);
                    mma_bf16(oacc[2 * db + 1], pah, bl[2], bl[3]);
                    mma_bf16(oacc[2 * db],     pal, bh[0], bh[1]);
                    mma_bf16(oacc[2 * db + 1], pal, bh[2], bh[3]);
                }
            }
        }

        __syncthreads();
        if (kt + 2 < KT) issue_kv(kt + 2);
        cp_commit();
    }

    // ---- epilogue: normalize, sigmoid gate, write bf16 hi/lo z ----
    const int r1 = q0 + wm + (lane >> 2);
    const float il1 = 1.0f / l1;
    const float il2 = 1.0f / l2;
    const size_t t1 = bS + r1, t2 = t1 + 8;
    const float* g1 = qraw + t1 * NQ + h * (2 * Dc) + Dc;
    const float* g2 = qraw + t2 * NQ + h * (2 * Dc) + Dc;
    const size_t z1o = t1 * ((size_t)Hc * Dc) + h * Dc;
    const size_t z2o = t2 * ((size_t)Hc * Dc) + h * Dc;
    #pragma unroll
    for (int t = 0; t < 16; t++) {
        int col = 8 * t + 2 * (lane & 3);
        float2 gv1 = *(const float2*)(g1 + col);
        float2 gv2 = *(const float2*)(g2 + col);
        float v0 = oacc[t][0] * il1 / (1.f + ex2f(-LOG2E * gv1.x));
        float v1 = oacc[t][1] * il1 / (1.f + ex2f(-LOG2E * gv1.y));
        float v2 = oacc[t][2] * il2 / (1.f + ex2f(-LOG2E * gv2.x));
        float v3 = oacc[t][3] * il2 / (1.f + ex2f(-LOG2E * gv2.y));
        __nv_bfloat16 h0, l0, h1, l1b, h2, l2b, h3, l3;
        bf_split(v0, h0, l0); bf_split(v1, h1, l1b);
        bf_split(v2, h2, l2b); bf_split(v3, h3, l3);
        *(ushort2*)&Zh[z1o + col] = make_ushort2(us(h0), us(h1));
        *(ushort2*)&Zl[z1o + col] = make_ushort2(us(l0), us(l1b));
        *(ushort2*)&Zh[z2o + col] = make_ushort2(us(h2), us(h3));
        *(ushort2*)&Zl[z2o + col] = make_ushort2(us(l2b), us(l3));
    }
}

// ====================================================================
// launch
// ====================================================================
extern "C" void kernel_launch(void* const* d_in, const int* in_sizes, int n_in,
                              void* d_out, int out_size)
{
    (void)in_sizes; (void)n_in; (void)out_size;
    const float* x    = (const float*)d_in[0];
    const float* Wq   = (const float*)d_in[1];
    const float* Wk   = (const float*)d_in[2];
    const float* Wv   = (const float*)d_in[3];
    const float* Wo   = (const float*)d_in[4];
    const float* qn_w = (const float*)d_in[5];
    const float* kn_w = (const float*)d_in[6];
    float* out = (float*)d_out;

    float *qraw_p, *k_p;
    cudaGetSymbolAddress((void**)&qraw_p, g_qraw);
    cudaGetSymbolAddress((void**)&k_p,    g_k);

    __nv_bfloat16 *xh, *xl, *zh, *zl, *wqh, *wql, *wkh, *wkl, *wvh, *wvl, *woh, *wol;
    __nv_bfloat16 *qbh, *qbl, *kbh, *kbl, *vbh, *vbl;
    cudaGetSymbolAddress((void**)&xh,  g_xh);  cudaGetSymbolAddress((void**)&xl,  g_xl);
    cudaGetSymbolAddress((void**)&zh,  g_zh);  cudaGetSymbolAddress((void**)&zl,  g_zl);
    cudaGetSymbolAddress((void**)&wqh, g_wqh); cudaGetSymbolAddress((void**)&wql, g_wql);
    cudaGetSymbolAddress((void**)&wkh, g_wkh); cudaGetSymbolAddress((void**)&wkl, g_wkl);
    cudaGetSymbolAddress((void**)&wvh, g_wvh); cudaGetSymbolAddress((void**)&wvl, g_wvl);
    cudaGetSymbolAddress((void**)&woh, g_woh); cudaGetSymbolAddress((void**)&wol, g_wol);
    cudaGetSymbolAddress((void**)&qbh, g_qbh); cudaGetSymbolAddress((void**)&qbl, g_qbl);
    cudaGetSymbolAddress((void**)&kbh, g_kbh); cudaGetSymbolAddress((void**)&kbl, g_kbl);
    cudaGetSymbolAddress((void**)&vbh, g_vbh); cudaGetSymbolAddress((void**)&vbl, g_vbl);

    cudaFuncSetAttribute(hgemm_split, cudaFuncAttributeMaxDynamicSharedMemorySize, HG_SMEM);
    cudaFuncSetAttribute(attn_mma, cudaFuncAttributeMaxDynamicSharedMemorySize, ATTN_SMEM);

    const int BIG = 1 << 30;

    // 0) split + transpose operands
    split_f32<<<(Mc * HID / 4 + 255) / 256, 256>>>(x, xh, xl, Mc * HID / 4);
    transpose_split<<<dim3(NQ / 32, HID / 32), dim3(32, 8)>>>(Wq, wqh, wql, HID, NQ);
    transpose_split<<<dim3(NK / 32, HID / 32), dim3(32, 8)>>>(Wk, wkh, wkl, HID, NK);
    transpose_split<<<dim3(NK / 32, HID / 32), dim3(32, 8)>>>(Wv, wvh, wvl, HID, NK);
    transpose_split<<<dim3(HID / 32, HID / 32), dim3(32, 8)>>>(Wo, woh, wol, HID, HID);

    // 1) projections: Q (fp32 out); K (fp32 out) + V (bf16-split out) fused
    hgemm_split<<<dim3(NQ / 256, Mc / 128), 256, HG_SMEM>>>(
        xh, xl, wqh, wql, qraw_p, wqh, wql, qraw_p, vbh, vbl, 0, BIG, Mc, NQ, HID);
    hgemm_split<<<dim3(2 * NK / 256, Mc / 128), 256, HG_SMEM>>>(
        xh, xl, wkh, wkl, k_p, wvh, wvl, k_p, vbh, vbl, 1, NK / 256, Mc, NK, HID);

    // 2) rmsnorm + rope -> bf16 splits
    norm_rope_q_bf<<<(Mc * Hc) / 8, 256>>>(qraw_p, qn_w, qbh, qbl);
    norm_rope_k_bf<<<(Mc * KVc) / 8, 256>>>(k_p, kn_w, kbh, kbl);

    // 3) HMMA flash attention + gate -> bf16 split z
    attn_mma<<<dim3(Sc / 128, Hc, Bc), 256, ATTN_SMEM>>>(
        qbh, qbl, kbh, kbl, vbh, vbl, qraw_p, zh, zl);

    // 4) output projection
    hgemm_split<<<dim3(HID / 256, Mc / 128), 256, HG_SMEM>>>(
        zh, zl, woh, wol, out, woh, wol, out, vbh, vbl, 0, BIG, Mc, HID, HID);
}

// round 10
// speedup vs baseline: 1.1393x; 1.1393x over previous
#include <cuda_runtime.h>
#include <cuda_bf16.h>
#include <math.h>
#include <stdint.h>

// ---------------- problem constants ----------------
constexpr int Bc   = 2;
constexpr int Sc   = 2048;
constexpr int HID  = 2048;
constexpr int Hc   = 16;
constexpr int KVc  = 4;
constexpr int Dc   = 128;
constexpr int Mc   = Bc * Sc;         // 4096
constexpr int NQ   = 2 * Hc * Dc;     // 4096 (q | gate)
constexpr int NK   = KVc * Dc;        // 512
constexpr float ATT_SCALE = 0.08838834764831845f;   // 1/sqrt(128)
constexpr float LOG2E = 1.4426950408889634f;

// ---------------- scratch (device globals; no allocations allowed) ----------------
__device__ float g_qraw[(size_t)Mc * NQ];
__device__ float g_k   [(size_t)Mc * NK];
__device__ float g_v   [(size_t)Mc * NK];
__device__ float g_z   [(size_t)Mc * Hc * Dc];

__device__ __nv_bfloat16 g_xh[(size_t)Mc * HID];
__device__ __nv_bfloat16 g_xl[(size_t)Mc * HID];
__device__ __nv_bfloat16 g_zh[(size_t)Mc * HID];
__device__ __nv_bfloat16 g_zl[(size_t)Mc * HID];
__device__ __nv_bfloat16 g_wqh[(size_t)NQ * HID];
__device__ __nv_bfloat16 g_wql[(size_t)NQ * HID];
__device__ __nv_bfloat16 g_wkh[(size_t)NK * HID];
__device__ __nv_bfloat16 g_wkl[(size_t)NK * HID];
__device__ __nv_bfloat16 g_wvh[(size_t)NK * HID];
__device__ __nv_bfloat16 g_wvl[(size_t)NK * HID];
__device__ __nv_bfloat16 g_woh[(size_t)HID * HID];
__device__ __nv_bfloat16 g_wol[(size_t)HID * HID];

__device__ __nv_bfloat16 g_qbh[(size_t)Mc * Hc * Dc];
__device__ __nv_bfloat16 g_qbl[(size_t)Mc * Hc * Dc];
__device__ __nv_bfloat16 g_kbh[(size_t)Mc * NK];
__device__ __nv_bfloat16 g_kbl[(size_t)Mc * NK];
__device__ __nv_bfloat16 g_vbh[(size_t)Mc * NK];
__device__ __nv_bfloat16 g_vbl[(size_t)Mc * NK];

// ---------------- baseline-PTX helpers ----------------
__device__ __forceinline__ uint32_t smem_u32(const void* p) {
    return (uint32_t)__cvta_generic_to_shared(p);
}
__device__ __forceinline__ void cp_async16(uint32_t dst, const void* src) {
    asm volatile("cp.async.cg.shared.global [%0], [%1], 16;" :: "r"(dst), "l"(src));
}
__device__ __forceinline__ void cp_commit() {
    asm volatile("cp.async.commit_group;" ::: "memory");
}
__device__ __forceinline__ void cp_wait1() {
    asm volatile("cp.async.wait_group 1;" ::: "memory");
}
__device__ __forceinline__ void cp_wait0() {
    asm volatile("cp.async.wait_group 0;" ::: "memory");
}
__device__ __forceinline__ void ldm_x4(uint32_t& r0, uint32_t& r1, uint32_t& r2, uint32_t& r3,
                                       uint32_t addr) {
    asm volatile("ldmatrix.sync.aligned.m8n8.x4.shared.b16 {%0,%1,%2,%3}, [%4];"
                 : "=r"(r0), "=r"(r1), "=r"(r2), "=r"(r3) : "r"(addr));
}
__device__ __forceinline__ void ldm_x4_t(uint32_t& r0, uint32_t& r1, uint32_t& r2, uint32_t& r3,
                                         uint32_t addr) {
    asm volatile("ldmatrix.sync.aligned.m8n8.x4.trans.shared.b16 {%0,%1,%2,%3}, [%4];"
                 : "=r"(r0), "=r"(r1), "=r"(r2), "=r"(r3) : "r"(addr));
}
__device__ __forceinline__ void mma_bf16(float* c, const uint32_t* a, uint32_t b0, uint32_t b1) {
    asm volatile(
        "mma.sync.aligned.m16n8k16.row.col.f32.bf16.bf16.f32 "
        "{%0,%1,%2,%3}, {%4,%5,%6,%7}, {%8,%9}, {%0,%1,%2,%3};"
        : "+f"(c[0]), "+f"(c[1]), "+f"(c[2]), "+f"(c[3])
        : "r"(a[0]), "r"(a[1]), "r"(a[2]), "r"(a[3]), "r"(b0), "r"(b1));
}
__device__ __forceinline__ float ex2f(float x) {
    float y; asm("ex2.approx.f32 %0, %1;" : "=f"(y) : "f"(x)); return y;
}
__device__ __forceinline__ void bf_split(float v, __nv_bfloat16& h, __nv_bfloat16& l) {
    h = __float2bfloat16(v);
    l = __float2bfloat16(v - __bfloat162float(h));
}
__device__ __forceinline__ void cvt_split2(float p0, float p1, uint32_t& hi, uint32_t& lo) {
    __nv_bfloat162 h = __floats2bfloat162_rn(p0, p1);
    __nv_bfloat162 l = __floats2bfloat162_rn(p0 - __bfloat162float(h.x),
                                             p1 - __bfloat162float(h.y));
    hi = *reinterpret_cast<uint32_t*>(&h);
    lo = *reinterpret_cast<uint32_t*>(&l);
}
__device__ __forceinline__ unsigned short us(__nv_bfloat16 v) {
    return __bfloat16_as_ushort(v);
}

// ====================================================================
// HMMA split-bf16 GEMM, single-pass 3-term (R6-exact):
//   per K-stage load Ah,Al,Bh,Bl once; issue Ah*Bh + Ah*Bl + Al*Bh.
// 128x128 CTA tile, BK=32, 2-stage double buffer, 8 warps, 2 CTA/SM.
// Optional second (B,C) set selected by blockIdx.x >= nsplit.
// ====================================================================
constexpr int LDT = 40;
constexpr int TILE_B = 128 * LDT * 2;
constexpr int STAGE_B = 4 * TILE_B;
constexpr int HG_SMEM = 2 * STAGE_B;

__global__ __launch_bounds__(256, 2)
void hgemm_split(const __nv_bfloat16* __restrict__ Ah, const __nv_bfloat16* __restrict__ Al,
                 const __nv_bfloat16* __restrict__ Bh, const __nv_bfloat16* __restrict__ Bl,
                 float* __restrict__ C,
                 const __nv_bfloat16* __restrict__ Bh2, const __nv_bfloat16* __restrict__ Bl2,
                 float* __restrict__ C2, int nsplit,
                 int M, int N, int K)
{
    extern __shared__ __align__(128) char smem[];
    const uint32_t sb = smem_u32(smem);

    const int tid  = threadIdx.x;
    const int warp = tid >> 5, lane = tid & 31;

    const __nv_bfloat16* Bh_ = Bh;
    const __nv_bfloat16* Bl_ = Bl;
    float* C_ = C;
    int bx = blockIdx.x;
    if (bx >= nsplit) { Bh_ = Bh2; Bl_ = Bl2; C_ = C2; bx -= nsplit; }
    const int n0 = bx * 128;
    const int m0 = blockIdx.y * 128;
    const int wm = (warp >> 1) * 32;
    const int wn = (warp & 1) * 64;

    const int KT = K / 32;

    const int lrow = tid >> 2;
    const int lcc  = tid & 3;

    auto issue_stage = [&](int kt) {
        const uint32_t dbase = sb + (kt & 1) * STAGE_B + (lrow * LDT + lcc * 8) * 2;
        const size_t koff = (size_t)kt * 32 + lcc * 8;
        const __nv_bfloat16* pah = Ah  + (size_t)(m0 + lrow) * K + koff;
        const __nv_bfloat16* pal = Al  + (size_t)(m0 + lrow) * K + koff;
        const __nv_bfloat16* pbh = Bh_ + (size_t)(n0 + lrow) * K + koff;
        const __nv_bfloat16* pbl = Bl_ + (size_t)(n0 + lrow) * K + koff;
        const uint32_t rstep = 64 * LDT * 2;
        cp_async16(dbase,                        pah);
        cp_async16(dbase + rstep,                pah + (size_t)64 * K);
        cp_async16(dbase + TILE_B,               pal);
        cp_async16(dbase + TILE_B + rstep,       pal + (size_t)64 * K);
        cp_async16(dbase + 2 * TILE_B,           pbh);
        cp_async16(dbase + 2 * TILE_B + rstep,   pbh + (size_t)64 * K);
        cp_async16(dbase + 3 * TILE_B,           pbl);
        cp_async16(dbase + 3 * TILE_B + rstep,   pbl + (size_t)64 * K);
    };

    float acc[2][8][4];
    #pragma unroll
    for (int i = 0; i < 2; i++)
        #pragma unroll
        for (int j = 0; j < 8; j++)
            #pragma unroll
            for (int q = 0; q < 4; q++) acc[i][j][q] = 0.f;

    const int a_row = lane & 15;
    const int a_ko  = (lane >> 4) << 3;
    const int b_row = ((lane >> 4) << 3) + (lane & 7);
    const int b_ko  = ((lane >> 3) & 1) << 3;

    issue_stage(0); cp_commit();

    for (int kt = 0; kt < KT; kt++) {
        if (kt + 1 < KT) { issue_stage(kt + 1); cp_commit(); cp_wait1(); }
        else             { cp_wait0(); }
        __syncthreads();

        const uint32_t sa_h = sb + (kt & 1) * STAGE_B;
        const uint32_t sa_l = sa_h + TILE_B;
        const uint32_t sb_h = sa_h + 2 * TILE_B;
        const uint32_t sb_l = sa_h + 3 * TILE_B;

        #pragma unroll
        for (int ks = 0; ks < 32; ks += 16) {
            uint32_t ah[2][4], al[2][4];
            #pragma unroll
            for (int mi = 0; mi < 2; mi++) {
                uint32_t off = ((wm + mi * 16 + a_row) * LDT + ks + a_ko) * 2;
                ldm_x4(ah[mi][0], ah[mi][1], ah[mi][2], ah[mi][3], sa_h + off);
                ldm_x4(al[mi][0], al[mi][1], al[mi][2], al[mi][3], sa_l + off);
            }
            #pragma unroll
            for (int nb = 0; nb < 4; nb++) {
                uint32_t bh[4], bl[4];
                uint32_t off = ((wn + nb * 16 + b_row) * LDT + ks + b_ko) * 2;
                ldm_x4(bh[0], bh[1], bh[2], bh[3], sb_h + off);
                ldm_x4(bl[0], bl[1], bl[2], bl[3], sb_l + off);
                #pragma unroll
                for (int mi = 0; mi < 2; mi++) {
                    mma_bf16(acc[mi][2 * nb],     ah[mi], bh[0], bh[1]);
                    mma_bf16(acc[mi][2 * nb + 1], ah[mi], bh[2], bh[3]);
                    mma_bf16(acc[mi][2 * nb],     ah[mi], bl[0], bl[1]);
                    mma_bf16(acc[mi][2 * nb + 1], ah[mi], bl[2], bl[3]);
                    mma_bf16(acc[mi][2 * nb],     al[mi], bh[0], bh[1]);
                    mma_bf16(acc[mi][2 * nb + 1], al[mi], bh[2], bh[3]);
                }
            }
        }
        __syncthreads();
    }

    #pragma unroll
    for (int mi = 0; mi < 2; mi++) {
        const int r0 = m0 + wm + mi * 16 + (lane >> 2);
        #pragma unroll
        for (int ni = 0; ni < 8; ni++) {
            const int col = n0 + wn + ni * 8 + 2 * (lane & 3);
            *(float2*)&C_[(size_t)r0 * N + col]       = make_float2(acc[mi][ni][0], acc[mi][ni][1]);
            *(float2*)&C_[(size_t)(r0 + 8) * N + col] = make_float2(acc[mi][ni][2], acc[mi][ni][3]);
        }
    }
}

// ====================================================================
// fp32 -> bf16 hi/lo split (elementwise)
// ====================================================================
__global__ __launch_bounds__(256) void split_f32(const float* __restrict__ in,
                                                 __nv_bfloat16* __restrict__ hi,
                                                 __nv_bfloat16* __restrict__ lo, int n4)
{
    int i = blockIdx.x * 256 + threadIdx.x;
    if (i >= n4) return;
    float4 v = ((const float4*)in)[i];
    __nv_bfloat16 h0, h1, h2, h3, l0, l1, l2, l3;
    bf_split(v.x, h0, l0); bf_split(v.y, h1, l1);
    bf_split(v.z, h2, l2); bf_split(v.w, h3, l3);
    ((ushort4*)hi)[i] = make_ushort4(us(h0), us(h1), us(h2), us(h3));
    ((ushort4*)lo)[i] = make_ushort4(us(l0), us(l1), us(l2), us(l3));
}

// ====================================================================
// fp32 [R,C] -> transposed bf16 hi/lo [C,R]
// ====================================================================
__global__ __launch_bounds__(256) void transpose_split(const float* __restrict__ in,
                                                       __nv_bfloat16* __restrict__ hiT,
                                                       __nv_bfloat16* __restrict__ loT,
                                                       int R, int C)
{
    __shared__ float t[32][33];
    int c0 = blockIdx.x * 32, r0 = blockIdx.y * 32;
    int tx = threadIdx.x, ty = threadIdx.y;
    #pragma unroll
    for (int k = 0; k < 4; k++)
        t[ty + 8 * k][tx] = in[(size_t)(r0 + ty + 8 * k) * C + c0 + tx];
    __syncthreads();
    #pragma unroll
    for (int k = 0; k < 4; k++) {
        float v = t[tx][ty + 8 * k];
        __nv_bfloat16 h, l;
        bf_split(v, h, l);
        size_t o = (size_t)(c0 + ty + 8 * k) * R + r0 + tx;
        hiT[o] = h;
        loT[o] = l;
    }
}

// ====================================================================
// RMSNorm + RoPE -> bf16 hi/lo
// ====================================================================
__device__ __forceinline__ void norm_rope_bf(const float* __restrict__ src,
                                             __nv_bfloat16* __restrict__ dh,
                                             __nv_bfloat16* __restrict__ dl,
                                             const float* __restrict__ w,
                                             int pos, int lane, float outscale)
{
    float x0 = src[lane], x1 = src[lane + 32], x2 = src[lane + 64], x3 = src[lane + 96];
    float ss = x0 * x0 + x1 * x1 + x2 * x2 + x3 * x3;
    #pragma unroll
    for (int o = 16; o; o >>= 1) ss += __shfl_xor_sync(0xffffffffu, ss, o);
    float rn = rsqrtf(ss * (1.0f / 128.0f) + 1e-6f);
    float y0 = x0 * rn * (w[lane] + 1.f);
    float y1 = x1 * rn * (w[lane + 32] + 1.f);
    float y2 = x2 * rn * (w[lane + 64] + 1.f);
    float y3 = x3 * rn * (w[lane + 96] + 1.f);
    float inv0 = powf(1000000.0f, -(float)(2 * lane) / 128.f);
    float inv1 = powf(1000000.0f, -(float)(2 * (lane + 32)) / 128.f);
    float f0 = (float)pos * inv0, f1 = (float)pos * inv1;
    float c0, s0, c1, s1;
    sincosf(f0, &s0, &c0);
    sincosf(f1, &s1, &c1);
    float o0  = (y0 * c0 - y2 * s0) * outscale;
    float o64 = (y2 * c0 + y0 * s0) * outscale;
    float o32 = (y1 * c1 - y3 * s1) * outscale;
    float o96 = (y3 * c1 + y1 * s1) * outscale;
    __nv_bfloat16 h, l;
    bf_split(o0, h, l);  dh[lane]      = h; dl[lane]      = l;
    bf_split(o64, h, l); dh[lane + 64] = h; dl[lane + 64] = l;
    bf_split(o32, h, l); dh[lane + 32] = h; dl[lane + 32] = l;
    bf_split(o96, h, l); dh[lane + 96] = h; dl[lane + 96] = l;
}

__global__ __launch_bounds__(256) void norm_rope_q_bf(const float* __restrict__ qraw,
                                                      const float* __restrict__ w,
                                                      __nv_bfloat16* __restrict__ qh,
                                                      __nv_bfloat16* __restrict__ ql)
{
    int warp = blockIdx.x * 8 + (threadIdx.x >> 5);
    int lane = threadIdx.x & 31;
    if (warp >= Mc * Hc) return;
    int m = warp >> 4;
    int h = warp & 15;
    int pos = m & (Sc - 1);
    const float* src = qraw + (size_t)m * NQ + h * (2 * Dc);
    size_t dof = (size_t)m * (Hc * Dc) + h * Dc;
    norm_rope_bf(src, qh + dof, ql + dof, w, pos, lane, ATT_SCALE);
}

__global__ __launch_bounds__(256) void norm_rope_k_bf(const float* __restrict__ kraw,
                                                      const float* __restrict__ w,
                                                      __nv_bfloat16* __restrict__ kh,
                                                      __nv_bfloat16* __restrict__ kl)
{
    int warp = blockIdx.x * 8 + (threadIdx.x >> 5);
    int lane = threadIdx.x & 31;
    if (warp >= Mc * KVc) return;
    int m = warp >> 2;
    int pos = m & (Sc - 1);
    const float* src = kraw + (size_t)warp * Dc;
    norm_rope_bf(src, kh + (size_t)warp * Dc, kl + (size_t)warp * Dc, w, pos, lane, 1.0f);
}

// ====================================================================
// HMMA flash attention (R6: BQ=128, BK=64, 2-stage ring, fp32 z out)
// ====================================================================
constexpr int ALD = 136;
constexpr int Q_ELE = 128 * ALD;
constexpr int KV_TILE_E = 64 * ALD;
constexpr int KV_STAGE_E = 4 * KV_TILE_E;
constexpr int SM_KV_E = 2 * Q_ELE;
constexpr int ATTN_SMEM = (2 * Q_ELE + 2 * KV_STAGE_E) * 2;

__global__ __launch_bounds__(256, 1)
void attn_mma(const __nv_bfloat16* __restrict__ qh, const __nv_bfloat16* __restrict__ ql,
              const __nv_bfloat16* __restrict__ kh, const __nv_bfloat16* __restrict__ kl,
              const __nv_bfloat16* __restrict__ vh, const __nv_bfloat16* __restrict__ vl,
              const float* __restrict__ qraw, float* __restrict__ Z)
{
    extern __shared__ __align__(128) char smem[];
    const uint32_t sb = smem_u32(smem);

    const int tid = threadIdx.x;
    const int warp = tid >> 5, lane = tid & 31;
    const int qt = (int)gridDim.x - 1 - (int)blockIdx.x;
    const int h  = blockIdx.y;
    const int b  = blockIdx.z;
    const int kv = h >> 2;
    const int q0 = qt * 128;
    const int wm = warp * 16;
    const size_t bS = (size_t)b * Sc;
    const int KT = 2 * qt + 2;

    const int a_row = lane & 15;
    const int a_ko  = (lane >> 4) << 3;
    const int b_row = ((lane >> 4) << 3) + (lane & 7);
    const int b_ko  = ((lane >> 3) & 1) << 3;
    const int v_row = (lane & 7) + (((lane >> 3) & 1) << 3);
    const int v_co  = (lane >> 4) << 3;

    auto issue_kv = [&](int kt) {
        const uint32_t stg = sb + (SM_KV_E + (kt & 1) * KV_STAGE_E) * 2;
        #pragma unroll
        for (int p = 0; p < 4; p++) {
            int cid = tid + 256 * p;
            int row = cid >> 4, ch = cid & 15;
            size_t go = (bS + kt * 64 + row) * NK + kv * Dc + ch * 8;
            uint32_t so = (row * ALD + ch * 8) * 2;
            cp_async16(stg + so,                     kh + go);
            cp_async16(stg + KV_TILE_E * 2 + so,     kl + go);
            cp_async16(stg + 2 * KV_TILE_E * 2 + so, vh + go);
            cp_async16(stg + 3 * KV_TILE_E * 2 + so, vl + go);
        }
    };

    #pragma unroll
    for (int p = 0; p < 8; p++) {
        int cid = tid + 256 * p;
        int row = cid >> 4, ch = cid & 15;
        size_t go = (bS + q0 + row) * ((size_t)Hc * Dc) + h * Dc + ch * 8;
        uint32_t so = (row * ALD + ch * 8) * 2;
        cp_async16(sb + so,             qh + go);
        cp_async16(sb + Q_ELE * 2 + so, ql + go);
    }
    issue_kv(0);
    cp_commit();
    if (KT > 1) issue_kv(1);
    cp_commit();

    float oacc[16][4];
    #pragma unroll
    for (int t = 0; t < 16; t++)
        #pragma unroll
        for (int q = 0; q < 4; q++) oacc[t][q] = 0.f;
    float m1 = -1e30f, m2 = -1e30f, l1 = 0.f, l2 = 0.f;

    for (int kt = 0; kt < KT; kt++) {
        cp_wait1();
        __syncthreads();

        const bool wskip = (kt * 64) > (q0 + wm + 15);
        if (!wskip) {
            const uint32_t stg = sb + (SM_KV_E + (kt & 1) * KV_STAGE_E) * 2;
            const uint32_t sK_h = stg;
            const uint32_t sK_l = stg + KV_TILE_E * 2;
            const uint32_t sV_h = stg + 2 * KV_TILE_E * 2;
            const uint32_t sV_l = stg + 3 * KV_TILE_E * 2;

            float sacc[8][4];
            #pragma unroll
            for (int f = 0; f < 8; f++)
                #pragma unroll
                for (int q = 0; q < 4; q++) sacc[f][q] = 0.f;

            #pragma unroll
            for (int ks = 0; ks < 8; ks++) {
                uint32_t ah[4], al[4];
                uint32_t qaddr = sb + ((wm + a_row) * ALD + ks * 16 + a_ko) * 2;
                ldm_x4(ah[0], ah[1], ah[2], ah[3], qaddr);
                ldm_x4(al[0], al[1], al[2], al[3], qaddr + Q_ELE * 2);
                #pragma unroll
                for (int nb = 0; nb < 4; nb++) {
                    uint32_t bh[4], bl[4];
                    uint32_t kaddr = ((nb * 16 + b_row) * ALD + ks * 16 + b_ko) * 2;
                    ldm_x4(bh[0], bh[1], bh[2], bh[3], sK_h + kaddr);
                    ldm_x4(bl[0], bl[1], bl[2], bl[3], sK_l + kaddr);
                    mma_bf16(sacc[2 * nb],     ah, bh[0], bh[1]);
                    mma_bf16(sacc[2 * nb + 1], ah, bh[2], bh[3]);
                    mma_bf16(sacc[2 * nb],     ah, bl[0], bl[1]);
                    mma_bf16(sacc[2 * nb + 1], ah, bl[2], bl[3]);
                    mma_bf16(sacc[2 * nb],     al, bh[0], bh[1]);
                    mma_bf16(sacc[2 * nb + 1], al, bh[2], bh[3]);
                }
            }

            const int r1 = q0 + wm + (lane >> 2);
            const int r2 = r1 + 8;
            if (kt * 64 + 63 > q0 + wm) {
                #pragma unroll
                for (int f = 0; f < 8; f++) {
                    int cb = kt * 64 + 8 * f + 2 * (lane & 3);
                    if (cb     > r1) sacc[f][0] = -1e30f;
                    if (cb + 1 > r1) sacc[f][1] = -1e30f;
                    if (cb     > r2) sacc[f][2] = -1e30f;
                    if (cb + 1 > r2) sacc[f][3] = -1e30f;
                }
            }

            float mx1 = -1e30f, mx2 = -1e30f;
            #pragma unroll
            for (int f = 0; f < 8; f++) {
                mx1 = fmaxf(mx1, fmaxf(sacc[f][0], sacc[f][1]));
                mx2 = fmaxf(mx2, fmaxf(sacc[f][2], sacc[f][3]));
            }
            mx1 = fmaxf(mx1, __shfl_xor_sync(0xffffffffu, mx1, 1));
            mx1 = fmaxf(mx1, __shfl_xor_sync(0xffffffffu, mx1, 2));
            mx2 = fmaxf(mx2, __shfl_xor_sync(0xffffffffu, mx2, 1));
            mx2 = fmaxf(mx2, __shfl_xor_sync(0xffffffffu, mx2, 2));
            float m1n = fmaxf(m1, mx1), m2n = fmaxf(m2, mx2);
            float al1 = ex2f((m1 - m1n) * LOG2E);
            float al2 = ex2f((m2 - m2n) * LOG2E);
            m1 = m1n; m2 = m2n;

            float rs1 = 0.f, rs2 = 0.f;
            #pragma unroll
            for (int f = 0; f < 8; f++) {
                sacc[f][0] = ex2f((sacc[f][0] - m1n) * LOG2E);
                sacc[f][1] = ex2f((sacc[f][1] - m1n) * LOG2E);
                sacc[f][2] = ex2f((sacc[f][2] - m2n) * LOG2E);
                sacc[f][3] = ex2f((sacc[f][3] - m2n) * LOG2E);
                rs1 += sacc[f][0] + sacc[f][1];
                rs2 += sacc[f][2] + sacc[f][3];
            }
            rs1 += __shfl_xor_sync(0xffffffffu, rs1, 1);
            rs1 += __shfl_xor_sync(0xffffffffu, rs1, 2);
            rs2 += __shfl_xor_sync(0xffffffffu, rs2, 1);
            rs2 += __shfl_xor_sync(0xffffffffu, rs2, 2);
            l1 = l1 * al1 + rs1;
            l2 = l2 * al2 + rs2;

            if (al1 < 1.f) {
                #pragma unroll
                for (int t = 0; t < 16; t++) { oacc[t][0] *= al1; oacc[t][1] *= al1; }
            }
            if (al2 < 1.f) {
                #pragma unroll
                for (int t = 0; t < 16; t++) { oacc[t][2] *= al2; oacc[t][3] *= al2; }
            }

            #pragma unroll
            for (int j = 0; j < 4; j++) {
                uint32_t pah[4], pal[4];
                cvt_split2(sacc[2 * j][0],     sacc[2 * j][1],     pah[0], pal[0]);
                cvt_split2(sacc[2 * j][2],     sacc[2 * j][3],     pah[1], pal[1]);
                cvt_split2(sacc[2 * j + 1][0], sacc[2 * j + 1][1], pah[2], pal[2]);
                cvt_split2(sacc[2 * j + 1][2], sacc[2 * j + 1][3], pah[3], pal[3]);
                #pragma unroll
                for (int db = 0; db < 8; db++) {
                    uint32_t bh[4], bl[4];
                    uint32_t vaddr = ((j * 16 + v_row) * ALD + db * 16 + v_co) * 2;
                    ldm_x4_t(bh[0], bh[1], bh[2], bh[3], sV_h + vaddr);
                    ldm_x4_t(bl[0], bl[1], bl[2], bl[3], sV_l + vaddr);
                    mma_bf16(oacc[2 * db],     pah, bh[0], bh[1]);
                    mma_bf16(oacc[2 * db + 1], pah, bh[2], bh[3]);
                    mma_bf16(oacc[2 * db],     pah, bl[0], bl[1]);
                    mma_bf16(oacc[2 * db + 1], pah, bl[2], bl[3]);
                    mma_bf16(oacc[2 * db],     pal, bh[0], bh[1]);
                    mma_bf16(oacc[2 * db + 1], pal, bh[2], bh[3]);
                }
            }
        }

        __syncthreads();
        if (kt + 2 < KT) issue_kv(kt + 2);
        cp_commit();
    }

    const int r1 = q0 + wm + (lane >> 2);
    const float il1 = 1.0f / l1;
    const float il2 = 1.0f / l2;
    const size_t t1 = bS + r1, t2 = t1 + 8;
    const float* g1 = qraw + t1 * NQ + h * (2 * Dc) + Dc;
    const float* g2 = qraw + t2 * NQ + h * (2 * Dc) + Dc;
    float* z1 = Z + t1 * ((size_t)Hc * Dc) + h * Dc;
    float* z2 = Z + t2 * ((size_t)Hc * Dc) + h * Dc;
    #pragma unroll
    for (int t = 0; t < 16; t++) {
        int col = 8 * t + 2 * (lane & 3);
        float2 gv1 = *(const float2*)(g1 + col);
        float2 gv2 = *(const float2*)(g2 + col);
        float s1a = 1.f / (1.f + ex2f(-LOG2E * gv1.x));
        float s1b = 1.f / (1.f + ex2f(-LOG2E * gv1.y));
        float s2a = 1.f / (1.f + ex2f(-LOG2E * gv2.x));
        float s2b = 1.f / (1.f + ex2f(-LOG2E * gv2.y));
        *(float2*)(z1 + col) = make_float2(oacc[t][0] * il1 * s1a, oacc[t][1] * il1 * s1b);
        *(float2*)(z2 + col) = make_float2(oacc[t][2] * il2 * s2a, oacc[t][3] * il2 * s2b);
    }
}

// ====================================================================
// launch — multi-stream fork/join (capture-legal event pattern)
// ====================================================================
static cudaStream_t g_s1 = nullptr;
static cudaEvent_t  g_evFork = nullptr, g_evX = nullptr, g_evJoin = nullptr;

extern "C" void kernel_launch(void* const* d_in, const int* in_sizes, int n_in,
                              void* d_out, int out_size)
{
    (void)in_sizes; (void)n_in; (void)out_size;
    const float* x    = (const float*)d_in[0];
    const float* Wq   = (const float*)d_in[1];
    const float* Wk   = (const float*)d_in[2];
    const float* Wv   = (const float*)d_in[3];
    const float* Wo   = (const float*)d_in[4];
    const float* qn_w = (const float*)d_in[5];
    const float* kn_w = (const float*)d_in[6];
    float* out = (float*)d_out;

    float *qraw_p, *k_p, *v_p, *z_p;
    cudaGetSymbolAddress((void**)&qraw_p, g_qraw);
    cudaGetSymbolAddress((void**)&k_p,    g_k);
    cudaGetSymbolAddress((void**)&v_p,    g_v);
    cudaGetSymbolAddress((void**)&z_p,    g_z);

    __nv_bfloat16 *xh, *xl, *zh, *zl, *wqh, *wql, *wkh, *wkl, *wvh, *wvl, *woh, *wol;
    __nv_bfloat16 *qbh, *qbl, *kbh, *kbl, *vbh, *vbl;
    cudaGetSymbolAddress((void**)&xh,  g_xh);  cudaGetSymbolAddress((void**)&xl,  g_xl);
    cudaGetSymbolAddress((void**)&zh,  g_zh);  cudaGetSymbolAddress((void**)&zl,  g_zl);
    cudaGetSymbolAddress((void**)&wqh, g_wqh); cudaGetSymbolAddress((void**)&wql, g_wql);
    cudaGetSymbolAddress((void**)&wkh, g_wkh); cudaGetSymbolAddress((void**)&wkl, g_wkl);
    cudaGetSymbolAddress((void**)&wvh, g_wvh); cudaGetSymbolAddress((void**)&wvl, g_wvl);
    cudaGetSymbolAddress((void**)&woh, g_woh); cudaGetSymbolAddress((void**)&wol, g_wol);
    cudaGetSymbolAddress((void**)&qbh, g_qbh); cudaGetSymbolAddress((void**)&qbl, g_qbl);
    cudaGetSymbolAddress((void**)&kbh, g_kbh); cudaGetSymbolAddress((void**)&kbl, g_kbl);
    cudaGetSymbolAddress((void**)&vbh, g_vbh); cudaGetSymbolAddress((void**)&vbl, g_vbl);

    cudaFuncSetAttribute(hgemm_split, cudaFuncAttributeMaxDynamicSharedMemorySize, HG_SMEM);
    cudaFuncSetAttribute(attn_mma, cudaFuncAttributeMaxDynamicSharedMemorySize, ATTN_SMEM);

    if (g_s1 == nullptr) {
        cudaStreamCreateWithFlags(&g_s1, cudaStreamNonBlocking);
        cudaEventCreateWithFlags(&g_evFork, cudaEventDisableTiming);
        cudaEventCreateWithFlags(&g_evX,    cudaEventDisableTiming);
        cudaEventCreateWithFlags(&g_evJoin, cudaEventDisableTiming);
    }

    const int BIG = 1 << 30;
    cudaStream_t s0 = 0;        // capture stream (legacy default)
    cudaStream_t s1 = g_s1;

    // ---- fork ----
    cudaEventRecord(g_evFork, s0);
    cudaStreamWaitEvent(s1, g_evFork, 0);

    // Branch A (s0): x split -> Wq transpose -> Q-GEMM -> norm_q
    split_f32<<<(Mc * HID / 4 + 255) / 256, 256, 0, s0>>>(x, xh, xl, Mc * HID / 4);
    cudaEventRecord(g_evX, s0);                     // x ready for branch B
    transpose_split<<<dim3(NQ / 32, HID / 32), dim3(32, 8), 0, s0>>>(Wq, wqh, wql, HID, NQ);
    hgemm_split<<<dim3(NQ / 128, Mc / 128), 256, HG_SMEM, s0>>>(
        xh, xl, wqh, wql, qraw_p, wqh, wql, qraw_p, BIG, Mc, NQ, HID);
    norm_rope_q_bf<<<(Mc * Hc) / 8, 256, 0, s0>>>(qraw_p, qn_w, qbh, qbl);

    // Branch B (s1): Wk/Wv/Wo transposes -> KV-GEMM -> norm_k + v split
    transpose_split<<<dim3(NK / 32, HID / 32), dim3(32, 8), 0, s1>>>(Wk, wkh, wkl, HID, NK);
    transpose_split<<<dim3(NK / 32, HID / 32), dim3(32, 8), 0, s1>>>(Wv, wvh, wvl, HID, NK);
    transpose_split<<<dim3(HID / 32, HID / 32), dim3(32, 8), 0, s1>>>(Wo, woh, wol, HID, HID);
    cudaStreamWaitEvent(s1, g_evX, 0);
    hgemm_split<<<dim3(2 * NK / 128, Mc / 128), 256, HG_SMEM, s1>>>(
        xh, xl, wkh, wkl, k_p, wvh, wvl, v_p, NK / 128, Mc, NK, HID);
    norm_rope_k_bf<<<(Mc * KVc) / 8, 256, 0, s1>>>(k_p, kn_w, kbh, kbl);
    split_f32<<<(Mc * NK / 4 + 255) / 256, 256, 0, s1>>>(v_p, vbh, vbl, Mc * NK / 4);
    cudaEventRecord(g_evJoin, s1);

    // ---- join ----
    cudaStreamWaitEvent(s0, g_evJoin, 0);

    // attention + gate (s0)
    attn_mma<<<dim3(Sc / 128, Hc, Bc), 256, ATTN_SMEM, s0>>>(
        qbh, qbl, kbh, kbl, vbh, vbl, qraw_p, z_p);

    // output projection (s0)
    split_f32<<<(Mc * HID / 4 + 255) / 256, 256, 0, s0>>>(z_p, zh, zl, Mc * HID / 4);
    hgemm_split<<<dim3(HID / 128, Mc / 128), 256, HG_SMEM, s0>>>(
        zh, zl, woh, wol, out, woh, wol, out, BIG, Mc, HID, HID);
}

// round 11
// speedup vs baseline: 1.2446x; 1.0924x over previous
#include <cuda_runtime.h>
#include <cuda_bf16.h>
#include <math.h>
#include <stdint.h>

// ---------------- problem constants ----------------
constexpr int Bc   = 2;
constexpr int Sc   = 2048;
constexpr int HID  = 2048;
constexpr int Hc   = 16;
constexpr int KVc  = 4;
constexpr int Dc   = 128;
constexpr int Mc   = Bc * Sc;         // 4096
constexpr int NQ   = 2 * Hc * Dc;     // 4096 (q | gate)
constexpr int NK   = KVc * Dc;        // 512
constexpr float ATT_SCALE = 0.08838834764831845f;   // 1/sqrt(128)
constexpr float LOG2E = 1.4426950408889634f;

// ---------------- scratch (device globals; no allocations allowed) ----------------
__device__ float g_qraw[(size_t)Mc * NQ];
__device__ float g_k   [(size_t)Mc * NK];
__device__ float g_v   [(size_t)Mc * NK];
__device__ float g_z   [(size_t)Mc * Hc * Dc];

__device__ __nv_bfloat16 g_xh[(size_t)Mc * HID];
__device__ __nv_bfloat16 g_xl[(size_t)Mc * HID];
__device__ __nv_bfloat16 g_zh[(size_t)Mc * HID];
__device__ __nv_bfloat16 g_zl[(size_t)Mc * HID];
__device__ __nv_bfloat16 g_wqh[(size_t)NQ * HID];
__device__ __nv_bfloat16 g_wql[(size_t)NQ * HID];
__device__ __nv_bfloat16 g_wkh[(size_t)NK * HID];
__device__ __nv_bfloat16 g_wkl[(size_t)NK * HID];
__device__ __nv_bfloat16 g_wvh[(size_t)NK * HID];
__device__ __nv_bfloat16 g_wvl[(size_t)NK * HID];
__device__ __nv_bfloat16 g_woh[(size_t)HID * HID];
__device__ __nv_bfloat16 g_wol[(size_t)HID * HID];

__device__ __nv_bfloat16 g_qbh[(size_t)Mc * Hc * Dc];
__device__ __nv_bfloat16 g_qbl[(size_t)Mc * Hc * Dc];
__device__ __nv_bfloat16 g_kbh[(size_t)Mc * NK];
__device__ __nv_bfloat16 g_kbl[(size_t)Mc * NK];
__device__ __nv_bfloat16 g_vbh[(size_t)Mc * NK];
__device__ __nv_bfloat16 g_vbl[(size_t)Mc * NK];

// ---------------- baseline-PTX helpers ----------------
__device__ __forceinline__ uint32_t smem_u32(const void* p) {
    return (uint32_t)__cvta_generic_to_shared(p);
}
__device__ __forceinline__ void cp_async16(uint32_t dst, const void* src) {
    asm volatile("cp.async.cg.shared.global [%0], [%1], 16;" :: "r"(dst), "l"(src));
}
__device__ __forceinline__ void cp_commit() {
    asm volatile("cp.async.commit_group;" ::: "memory");
}
__device__ __forceinline__ void cp_wait1() {
    asm volatile("cp.async.wait_group 1;" ::: "memory");
}
__device__ __forceinline__ void cp_wait0() {
    asm volatile("cp.async.wait_group 0;" ::: "memory");
}
__device__ __forceinline__ void ldm_x4(uint32_t& r0, uint32_t& r1, uint32_t& r2, uint32_t& r3,
                                       uint32_t addr) {
    asm volatile("ldmatrix.sync.aligned.m8n8.x4.shared.b16 {%0,%1,%2,%3}, [%4];"
                 : "=r"(r0), "=r"(r1), "=r"(r2), "=r"(r3) : "r"(addr));
}
__device__ __forceinline__ void ldm_x4_t(uint32_t& r0, uint32_t& r1, uint32_t& r2, uint32_t& r3,
                                         uint32_t addr) {
    asm volatile("ldmatrix.sync.aligned.m8n8.x4.trans.shared.b16 {%0,%1,%2,%3}, [%4];"
                 : "=r"(r0), "=r"(r1), "=r"(r2), "=r"(r3) : "r"(addr));
}
__device__ __forceinline__ void mma_bf16(float* c, const uint32_t* a, uint32_t b0, uint32_t b1) {
    asm volatile(
        "mma.sync.aligned.m16n8k16.row.col.f32.bf16.bf16.f32 "
        "{%0,%1,%2,%3}, {%4,%5,%6,%7}, {%8,%9}, {%0,%1,%2,%3};"
        : "+f"(c[0]), "+f"(c[1]), "+f"(c[2]), "+f"(c[3])
        : "r"(a[0]), "r"(a[1]), "r"(a[2]), "r"(a[3]), "r"(b0), "r"(b1));
}
__device__ __forceinline__ float ex2f(float x) {
    float y; asm("ex2.approx.f32 %0, %1;" : "=f"(y) : "f"(x)); return y;
}
__device__ __forceinline__ void bf_split(float v, __nv_bfloat16& h, __nv_bfloat16& l) {
    h = __float2bfloat16(v);
    l = __float2bfloat16(v - __bfloat162float(h));
}
__device__ __forceinline__ void cvt_split2(float p0, float p1, uint32_t& hi, uint32_t& lo) {
    __nv_bfloat162 h = __floats2bfloat162_rn(p0, p1);
    __nv_bfloat162 l = __floats2bfloat162_rn(p0 - __bfloat162float(h.x),
                                             p1 - __bfloat162float(h.y));
    hi = *reinterpret_cast<uint32_t*>(&h);
    lo = *reinterpret_cast<uint32_t*>(&l);
}
__device__ __forceinline__ unsigned short us(__nv_bfloat16 v) {
    return __bfloat16_as_ushort(v);
}

// ====================================================================
// HMMA split-bf16 GEMM, single-pass 3-term (R6-exact).
// ====================================================================
constexpr int LDT = 40;
constexpr int TILE_B = 128 * LDT * 2;
constexpr int STAGE_B = 4 * TILE_B;
constexpr int HG_SMEM = 2 * STAGE_B;

__global__ __launch_bounds__(256, 2)
void hgemm_split(const __nv_bfloat16* __restrict__ Ah, const __nv_bfloat16* __restrict__ Al,
                 const __nv_bfloat16* __restrict__ Bh, const __nv_bfloat16* __restrict__ Bl,
                 float* __restrict__ C,
                 const __nv_bfloat16* __restrict__ Bh2, const __nv_bfloat16* __restrict__ Bl2,
                 float* __restrict__ C2, int nsplit,
                 int M, int N, int K)
{
    extern __shared__ __align__(128) char smem[];
    const uint32_t sb = smem_u32(smem);

    const int tid  = threadIdx.x;
    const int warp = tid >> 5, lane = tid & 31;

    const __nv_bfloat16* Bh_ = Bh;
    const __nv_bfloat16* Bl_ = Bl;
    float* C_ = C;
    int bx = blockIdx.x;
    if (bx >= nsplit) { Bh_ = Bh2; Bl_ = Bl2; C_ = C2; bx -= nsplit; }
    const int n0 = bx * 128;
    const int m0 = blockIdx.y * 128;
    const int wm = (warp >> 1) * 32;
    const int wn = (warp & 1) * 64;

    const int KT = K / 32;

    const int lrow = tid >> 2;
    const int lcc  = tid & 3;

    auto issue_stage = [&](int kt) {
        const uint32_t dbase = sb + (kt & 1) * STAGE_B + (lrow * LDT + lcc * 8) * 2;
        const size_t koff = (size_t)kt * 32 + lcc * 8;
        const __nv_bfloat16* pah = Ah  + (size_t)(m0 + lrow) * K + koff;
        const __nv_bfloat16* pal = Al  + (size_t)(m0 + lrow) * K + koff;
        const __nv_bfloat16* pbh = Bh_ + (size_t)(n0 + lrow) * K + koff;
        const __nv_bfloat16* pbl = Bl_ + (size_t)(n0 + lrow) * K + koff;
        const uint32_t rstep = 64 * LDT * 2;
        cp_async16(dbase,                        pah);
        cp_async16(dbase + rstep,                pah + (size_t)64 * K);
        cp_async16(dbase + TILE_B,               pal);
        cp_async16(dbase + TILE_B + rstep,       pal + (size_t)64 * K);
        cp_async16(dbase + 2 * TILE_B,           pbh);
        cp_async16(dbase + 2 * TILE_B + rstep,   pbh + (size_t)64 * K);
        cp_async16(dbase + 3 * TILE_B,           pbl);
        cp_async16(dbase + 3 * TILE_B + rstep,   pbl + (size_t)64 * K);
    };

    float acc[2][8][4];
    #pragma unroll
    for (int i = 0; i < 2; i++)
        #pragma unroll
        for (int j = 0; j < 8; j++)
            #pragma unroll
            for (int q = 0; q < 4; q++) acc[i][j][q] = 0.f;

    const int a_row = lane & 15;
    const int a_ko  = (lane >> 4) << 3;
    const int b_row = ((lane >> 4) << 3) + (lane & 7);
    const int b_ko  = ((lane >> 3) & 1) << 3;

    issue_stage(0); cp_commit();

    for (int kt = 0; kt < KT; kt++) {
        if (kt + 1 < KT) { issue_stage(kt + 1); cp_commit(); cp_wait1(); }
        else             { cp_wait0(); }
        __syncthreads();

        const uint32_t sa_h = sb + (kt & 1) * STAGE_B;
        const uint32_t sa_l = sa_h + TILE_B;
        const uint32_t sb_h = sa_h + 2 * TILE_B;
        const uint32_t sb_l = sa_h + 3 * TILE_B;

        #pragma unroll
        for (int ks = 0; ks < 32; ks += 16) {
            uint32_t ah[2][4], al[2][4];
            #pragma unroll
            for (int mi = 0; mi < 2; mi++) {
                uint32_t off = ((wm + mi * 16 + a_row) * LDT + ks + a_ko) * 2;
                ldm_x4(ah[mi][0], ah[mi][1], ah[mi][2], ah[mi][3], sa_h + off);
                ldm_x4(al[mi][0], al[mi][1], al[mi][2], al[mi][3], sa_l + off);
            }
            #pragma unroll
            for (int nb = 0; nb < 4; nb++) {
                uint32_t bh[4], bl[4];
                uint32_t off = ((wn + nb * 16 + b_row) * LDT + ks + b_ko) * 2;
                ldm_x4(bh[0], bh[1], bh[2], bh[3], sb_h + off);
                ldm_x4(bl[0], bl[1], bl[2], bl[3], sb_l + off);
                #pragma unroll
                for (int mi = 0; mi < 2; mi++) {
                    mma_bf16(acc[mi][2 * nb],     ah[mi], bh[0], bh[1]);
                    mma_bf16(acc[mi][2 * nb + 1], ah[mi], bh[2], bh[3]);
                    mma_bf16(acc[mi][2 * nb],     ah[mi], bl[0], bl[1]);
                    mma_bf16(acc[mi][2 * nb + 1], ah[mi], bl[2], bl[3]);
                    mma_bf16(acc[mi][2 * nb],     al[mi], bh[0], bh[1]);
                    mma_bf16(acc[mi][2 * nb + 1], al[mi], bh[2], bh[3]);
                }
            }
        }
        __syncthreads();
    }

    #pragma unroll
    for (int mi = 0; mi < 2; mi++) {
        const int r0 = m0 + wm + mi * 16 + (lane >> 2);
        #pragma unroll
        for (int ni = 0; ni < 8; ni++) {
            const int col = n0 + wn + ni * 8 + 2 * (lane & 3);
            *(float2*)&C_[(size_t)r0 * N + col]       = make_float2(acc[mi][ni][0], acc[mi][ni][1]);
            *(float2*)&C_[(size_t)(r0 + 8) * N + col] = make_float2(acc[mi][ni][2], acc[mi][ni][3]);
        }
    }
}

// ====================================================================
// fp32 -> bf16 hi/lo split (elementwise)
// ====================================================================
__global__ __launch_bounds__(256) void split_f32(const float* __restrict__ in,
                                                 __nv_bfloat16* __restrict__ hi,
                                                 __nv_bfloat16* __restrict__ lo, int n4)
{
    int i = blockIdx.x * 256 + threadIdx.x;
    if (i >= n4) return;
    float4 v = ((const float4*)in)[i];
    __nv_bfloat16 h0, h1, h2, h3, l0, l1, l2, l3;
    bf_split(v.x, h0, l0); bf_split(v.y, h1, l1);
    bf_split(v.z, h2, l2); bf_split(v.w, h3, l3);
    ((ushort4*)hi)[i] = make_ushort4(us(h0), us(h1), us(h2), us(h3));
    ((ushort4*)lo)[i] = make_ushort4(us(l0), us(l1), us(l2), us(l3));
}

// ====================================================================
// fp32 [R,C] -> transposed bf16 hi/lo [C,R]
// ====================================================================
__global__ __launch_bounds__(256) void transpose_split(const float* __restrict__ in,
                                                       __nv_bfloat16* __restrict__ hiT,
                                                       __nv_bfloat16* __restrict__ loT,
                                                       int R, int C)
{
    __shared__ float t[32][33];
    int c0 = blockIdx.x * 32, r0 = blockIdx.y * 32;
    int tx = threadIdx.x, ty = threadIdx.y;
    #pragma unroll
    for (int k = 0; k < 4; k++)
        t[ty + 8 * k][tx] = in[(size_t)(r0 + ty + 8 * k) * C + c0 + tx];
    __syncthreads();
    #pragma unroll
    for (int k = 0; k < 4; k++) {
        float v = t[tx][ty + 8 * k];
        __nv_bfloat16 h, l;
        bf_split(v, h, l);
        size_t o = (size_t)(c0 + ty + 8 * k) * R + r0 + tx;
        hiT[o] = h;
        loT[o] = l;
    }
}

// ====================================================================
// RMSNorm + RoPE -> bf16 hi/lo
// ====================================================================
__device__ __forceinline__ void norm_rope_bf(const float* __restrict__ src,
                                             __nv_bfloat16* __restrict__ dh,
                                             __nv_bfloat16* __restrict__ dl,
                                             const float* __restrict__ w,
                                             int pos, int lane, float outscale)
{
    float x0 = src[lane], x1 = src[lane + 32], x2 = src[lane + 64], x3 = src[lane + 96];
    float ss = x0 * x0 + x1 * x1 + x2 * x2 + x3 * x3;
    #pragma unroll
    for (int o = 16; o; o >>= 1) ss += __shfl_xor_sync(0xffffffffu, ss, o);
    float rn = rsqrtf(ss * (1.0f / 128.0f) + 1e-6f);
    float y0 = x0 * rn * (w[lane] + 1.f);
    float y1 = x1 * rn * (w[lane + 32] + 1.f);
    float y2 = x2 * rn * (w[lane + 64] + 1.f);
    float y3 = x3 * rn * (w[lane + 96] + 1.f);
    float inv0 = powf(1000000.0f, -(float)(2 * lane) / 128.f);
    float inv1 = powf(1000000.0f, -(float)(2 * (lane + 32)) / 128.f);
    float f0 = (float)pos * inv0, f1 = (float)pos * inv1;
    float c0, s0, c1, s1;
    sincosf(f0, &s0, &c0);
    sincosf(f1, &s1, &c1);
    float o0  = (y0 * c0 - y2 * s0) * outscale;
    float o64 = (y2 * c0 + y0 * s0) * outscale;
    float o32 = (y1 * c1 - y3 * s1) * outscale;
    float o96 = (y3 * c1 + y1 * s1) * outscale;
    __nv_bfloat16 h, l;
    bf_split(o0, h, l);  dh[lane]      = h; dl[lane]      = l;
    bf_split(o64, h, l); dh[lane + 64] = h; dl[lane + 64] = l;
    bf_split(o32, h, l); dh[lane + 32] = h; dl[lane + 32] = l;
    bf_split(o96, h, l); dh[lane + 96] = h; dl[lane + 96] = l;
}

__global__ __launch_bounds__(256) void norm_rope_q_bf(const float* __restrict__ qraw,
                                                      const float* __restrict__ w,
                                                      __nv_bfloat16* __restrict__ qh,
                                                      __nv_bfloat16* __restrict__ ql)
{
    int warp = blockIdx.x * 8 + (threadIdx.x >> 5);
    int lane = threadIdx.x & 31;
    if (warp >= Mc * Hc) return;
    int m = warp >> 4;
    int h = warp & 15;
    int pos = m & (Sc - 1);
    const float* src = qraw + (size_t)m * NQ + h * (2 * Dc);
    size_t dof = (size_t)m * (Hc * Dc) + h * Dc;
    norm_rope_bf(src, qh + dof, ql + dof, w, pos, lane, ATT_SCALE);
}

__global__ __launch_bounds__(256) void norm_rope_k_bf(const float* __restrict__ kraw,
                                                      const float* __restrict__ w,
                                                      __nv_bfloat16* __restrict__ kh,
                                                      __nv_bfloat16* __restrict__ kl)
{
    int warp = blockIdx.x * 8 + (threadIdx.x >> 5);
    int lane = threadIdx.x & 31;
    if (warp >= Mc * KVc) return;
    int m = warp >> 2;
    int pos = m & (Sc - 1);
    const float* src = kraw + (size_t)warp * Dc;
    norm_rope_bf(src, kh + (size_t)warp * Dc, kl + (size_t)warp * Dc, w, pos, lane, 1.0f);
}

// ====================================================================
// HMMA flash attention (BQ=128, BK=64, 2-stage ring, fp32 z out).
// One batch per launch: all pointers pre-offset to the batch base.
// ====================================================================
constexpr int ALD = 136;
constexpr int Q_ELE = 128 * ALD;
constexpr int KV_TILE_E = 64 * ALD;
constexpr int KV_STAGE_E = 4 * KV_TILE_E;
constexpr int SM_KV_E = 2 * Q_ELE;
constexpr int ATTN_SMEM = (2 * Q_ELE + 2 * KV_STAGE_E) * 2;

__global__ __launch_bounds__(256, 1)
void attn_mma(const __nv_bfloat16* __restrict__ qh, const __nv_bfloat16* __restrict__ ql,
              const __nv_bfloat16* __restrict__ kh, const __nv_bfloat16* __restrict__ kl,
              const __nv_bfloat16* __restrict__ vh, const __nv_bfloat16* __restrict__ vl,
              const float* __restrict__ qraw, float* __restrict__ Z)
{
    extern __shared__ __align__(128) char smem[];
    const uint32_t sb = smem_u32(smem);

    const int tid = threadIdx.x;
    const int warp = tid >> 5, lane = tid & 31;
    const int qt = (int)gridDim.x - 1 - (int)blockIdx.x;
    const int h  = blockIdx.y;
    const int kv = h >> 2;
    const int q0 = qt * 128;
    const int wm = warp * 16;
    const int KT = 2 * qt + 2;

    const int a_row = lane & 15;
    const int a_ko  = (lane >> 4) << 3;
    const int b_row = ((lane >> 4) << 3) + (lane & 7);
    const int b_ko  = ((lane >> 3) & 1) << 3;
    const int v_row = (lane & 7) + (((lane >> 3) & 1) << 3);
    const int v_co  = (lane >> 4) << 3;

    auto issue_kv = [&](int kt) {
        const uint32_t stg = sb + (SM_KV_E + (kt & 1) * KV_STAGE_E) * 2;
        #pragma unroll
        for (int p = 0; p < 4; p++) {
            int cid = tid + 256 * p;
            int row = cid >> 4, ch = cid & 15;
            size_t go = (size_t)(kt * 64 + row) * NK + kv * Dc + ch * 8;
            uint32_t so = (row * ALD + ch * 8) * 2;
            cp_async16(stg + so,                     kh + go);
            cp_async16(stg + KV_TILE_E * 2 + so,     kl + go);
            cp_async16(stg + 2 * KV_TILE_E * 2 + so, vh + go);
            cp_async16(stg + 3 * KV_TILE_E * 2 + so, vl + go);
        }
    };

    #pragma unroll
    for (int p = 0; p < 8; p++) {
        int cid = tid + 256 * p;
        int row = cid >> 4, ch = cid & 15;
        size_t go = (size_t)(q0 + row) * ((size_t)Hc * Dc) + h * Dc + ch * 8;
        uint32_t so = (row * ALD + ch * 8) * 2;
        cp_async16(sb + so,             qh + go);
        cp_async16(sb + Q_ELE * 2 + so, ql + go);
    }
    issue_kv(0);
    cp_commit();
    if (KT > 1) issue_kv(1);
    cp_commit();

    float oacc[16][4];
    #pragma unroll
    for (int t = 0; t < 16; t++)
        #pragma unroll
        for (int q = 0; q < 4; q++) oacc[t][q] = 0.f;
    float m1 = -1e30f, m2 = -1e30f, l1 = 0.f, l2 = 0.f;

    for (int kt = 0; kt < KT; kt++) {
        cp_wait1();
        __syncthreads();

        const bool wskip = (kt * 64) > (q0 + wm + 15);
        if (!wskip) {
            const uint32_t stg = sb + (SM_KV_E + (kt & 1) * KV_STAGE_E) * 2;
            const uint32_t sK_h = stg;
            const uint32_t sK_l = stg + KV_TILE_E * 2;
            const uint32_t sV_h = stg + 2 * KV_TILE_E * 2;
            const uint32_t sV_l = stg + 3 * KV_TILE_E * 2;

            float sacc[8][4];
            #pragma unroll
            for (int f = 0; f < 8; f++)
                #pragma unroll
                for (int q = 0; q < 4; q++) sacc[f][q] = 0.f;

            #pragma unroll
            for (int ks = 0; ks < 8; ks++) {
                uint32_t ah[4], al[4];
                uint32_t qaddr = sb + ((wm + a_row) * ALD + ks * 16 + a_ko) * 2;
                ldm_x4(ah[0], ah[1], ah[2], ah[3], qaddr);
                ldm_x4(al[0], al[1], al[2], al[3], qaddr + Q_ELE * 2);
                #pragma unroll
                for (int nb = 0; nb < 4; nb++) {
                    uint32_t bh[4], bl[4];
                    uint32_t kaddr = ((nb * 16 + b_row) * ALD + ks * 16 + b_ko) * 2;
                    ldm_x4(bh[0], bh[1], bh[2], bh[3], sK_h + kaddr);
                    ldm_x4(bl[0], bl[1], bl[2], bl[3], sK_l + kaddr);
                    mma_bf16(sacc[2 * nb],     ah, bh[0], bh[1]);
                    mma_bf16(sacc[2 * nb + 1], ah, bh[2], bh[3]);
                    mma_bf16(sacc[2 * nb],     ah, bl[0], bl[1]);
                    mma_bf16(sacc[2 * nb + 1], ah, bl[2], bl[3]);
                    mma_bf16(sacc[2 * nb],     al, bh[0], bh[1]);
                    mma_bf16(sacc[2 * nb + 1], al, bh[2], bh[3]);
                }
            }

            const int r1 = q0 + wm + (lane >> 2);
            const int r2 = r1 + 8;
            if (kt * 64 + 63 > q0 + wm) {
                #pragma unroll
                for (int f = 0; f < 8; f++) {
                    int cb = kt * 64 + 8 * f + 2 * (lane & 3);
                    if (cb     > r1) sacc[f][0] = -1e30f;
                    if (cb + 1 > r1) sacc[f][1] = -1e30f;
                    if (cb     > r2) sacc[f][2] = -1e30f;
                    if (cb + 1 > r2) sacc[f][3] = -1e30f;
                }
            }

            float mx1 = -1e30f, mx2 = -1e30f;
            #pragma unroll
            for (int f = 0; f < 8; f++) {
                mx1 = fmaxf(mx1, fmaxf(sacc[f][0], sacc[f][1]));
                mx2 = fmaxf(mx2, fmaxf(sacc[f][2], sacc[f][3]));
            }
            mx1 = fmaxf(mx1, __shfl_xor_sync(0xffffffffu, mx1, 1));
            mx1 = fmaxf(mx1, __shfl_xor_sync(0xffffffffu, mx1, 2));
            mx2 = fmaxf(mx2, __shfl_xor_sync(0xffffffffu, mx2, 1));
            mx2 = fmaxf(mx2, __shfl_xor_sync(0xffffffffu, mx2, 2));
            float m1n = fmaxf(m1, mx1), m2n = fmaxf(m2, mx2);
            float al1 = ex2f((m1 - m1n) * LOG2E);
            float al2 = ex2f((m2 - m2n) * LOG2E);
            m1 = m1n; m2 = m2n;

            float rs1 = 0.f, rs2 = 0.f;
            #pragma unroll
            for (int f = 0; f < 8; f++) {
                sacc[f][0] = ex2f((sacc[f][0] - m1n) * LOG2E);
                sacc[f][1] = ex2f((sacc[f][1] - m1n) * LOG2E);
                sacc[f][2] = ex2f((sacc[f][2] - m2n) * LOG2E);
                sacc[f][3] = ex2f((sacc[f][3] - m2n) * LOG2E);
                rs1 += sacc[f][0] + sacc[f][1];
                rs2 += sacc[f][2] + sacc[f][3];
            }
            rs1 += __shfl_xor_sync(0xffffffffu, rs1, 1);
            rs1 += __shfl_xor_sync(0xffffffffu, rs1, 2);
            rs2 += __shfl_xor_sync(0xffffffffu, rs2, 1);
            rs2 += __shfl_xor_sync(0xffffffffu, rs2, 2);
            l1 = l1 * al1 + rs1;
            l2 = l2 * al2 + rs2;

            if (al1 < 1.f) {
                #pragma unroll
                for (int t = 0; t < 16; t++) { oacc[t][0] *= al1; oacc[t][1] *= al1; }
            }
            if (al2 < 1.f) {
                #pragma unroll
                for (int t = 0; t < 16; t++) { oacc[t][2] *= al2; oacc[t][3] *= al2; }
            }

            #pragma unroll
            for (int j = 0; j < 4; j++) {
                uint32_t pah[4], pal[4];
                cvt_split2(sacc[2 * j][0],     sacc[2 * j][1],     pah[0], pal[0]);
                cvt_split2(sacc[2 * j][2],     sacc[2 * j][3],     pah[1], pal[1]);
                cvt_split2(sacc[2 * j + 1][0], sacc[2 * j + 1][1], pah[2], pal[2]);
                cvt_split2(sacc[2 * j + 1][2], sacc[2 * j + 1][3], pah[3], pal[3]);
                #pragma unroll
                for (int db = 0; db < 8; db++) {
                    uint32_t bh[4], bl[4];
                    uint32_t vaddr = ((j * 16 + v_row) * ALD + db * 16 + v_co) * 2;
                    ldm_x4_t(bh[0], bh[1], bh[2], bh[3], sV_h + vaddr);
                    ldm_x4_t(bl[0], bl[1], bl[2], bl[3], sV_l + vaddr);
                    mma_bf16(oacc[2 * db],     pah, bh[0], bh[1]);
                    mma_bf16(oacc[2 * db + 1], pah, bh[2], bh[3]);
                    mma_bf16(oacc[2 * db],     pah, bl[0], bl[1]);
                    mma_bf16(oacc[2 * db + 1], pah, bl[2], bl[3]);
                    mma_bf16(oacc[2 * db],     pal, bh[0], bh[1]);
                    mma_bf16(oacc[2 * db + 1], pal, bh[2], bh[3]);
                }
            }
        }

        __syncthreads();
        if (kt + 2 < KT) issue_kv(kt + 2);
        cp_commit();
    }

    const int r1 = q0 + wm + (lane >> 2);
    const float il1 = 1.0f / l1;
    const float il2 = 1.0f / l2;
    const size_t t1 = (size_t)r1, t2 = t1 + 8;
    const float* g1 = qraw + t1 * NQ + h * (2 * Dc) + Dc;
    const float* g2 = qraw + t2 * NQ + h * (2 * Dc) + Dc;
    float* z1 = Z + t1 * ((size_t)Hc * Dc) + h * Dc;
    float* z2 = Z + t2 * ((size_t)Hc * Dc) + h * Dc;
    #pragma unroll
    for (int t = 0; t < 16; t++) {
        int col = 8 * t + 2 * (lane & 3);
        float2 gv1 = *(const float2*)(g1 + col);
        float2 gv2 = *(const float2*)(g2 + col);
        float s1a = 1.f / (1.f + ex2f(-LOG2E * gv1.x));
        float s1b = 1.f / (1.f + ex2f(-LOG2E * gv1.y));
        float s2a = 1.f / (1.f + ex2f(-LOG2E * gv2.x));
        float s2b = 1.f / (1.f + ex2f(-LOG2E * gv2.y));
        *(float2*)(z1 + col) = make_float2(oacc[t][0] * il1 * s1a, oacc[t][1] * il1 * s1b);
        *(float2*)(z2 + col) = make_float2(oacc[t][2] * il2 * s2a, oacc[t][3] * il2 * s2b);
    }
}

// ====================================================================
// launch — two-phase multi-stream fork/join (capture-legal events)
// ====================================================================
static cudaStream_t g_s1 = nullptr;
static cudaEvent_t  g_evFork = nullptr, g_evX = nullptr, g_evJoin = nullptr;
static cudaEvent_t  g_evA = nullptr, g_evDone = nullptr;

extern "C" void kernel_launch(void* const* d_in, const int* in_sizes, int n_in,
                              void* d_out, int out_size)
{
    (void)in_sizes; (void)n_in; (void)out_size;
    const float* x    = (const float*)d_in[0];
    const float* Wq   = (const float*)d_in[1];
    const float* Wk   = (const float*)d_in[2];
    const float* Wv   = (const float*)d_in[3];
    const float* Wo   = (const float*)d_in[4];
    const float* qn_w = (const float*)d_in[5];
    const float* kn_w = (const float*)d_in[6];
    float* out = (float*)d_out;

    float *qraw_p, *k_p, *v_p, *z_p;
    cudaGetSymbolAddress((void**)&qraw_p, g_qraw);
    cudaGetSymbolAddress((void**)&k_p,    g_k);
    cudaGetSymbolAddress((void**)&v_p,    g_v);
    cudaGetSymbolAddress((void**)&z_p,    g_z);

    __nv_bfloat16 *xh, *xl, *zh, *zl, *wqh, *wql, *wkh, *wkl, *wvh, *wvl, *woh, *wol;
    __nv_bfloat16 *qbh, *qbl, *kbh, *kbl, *vbh, *vbl;
    cudaGetSymbolAddress((void**)&xh,  g_xh);  cudaGetSymbolAddress((void**)&xl,  g_xl);
    cudaGetSymbolAddress((void**)&zh,  g_zh);  cudaGetSymbolAddress((void**)&zl,  g_zl);
    cudaGetSymbolAddress((void**)&wqh, g_wqh); cudaGetSymbolAddress((void**)&wql, g_wql);
    cudaGetSymbolAddress((void**)&wkh, g_wkh); cudaGetSymbolAddress((void**)&wkl, g_wkl);
    cudaGetSymbolAddress((void**)&wvh, g_wvh); cudaGetSymbolAddress((void**)&wvl, g_wvl);
    cudaGetSymbolAddress((void**)&woh, g_woh); cudaGetSymbolAddress((void**)&wol, g_wol);
    cudaGetSymbolAddress((void**)&qbh, g_qbh); cudaGetSymbolAddress((void**)&qbl, g_qbl);
    cudaGetSymbolAddress((void**)&kbh, g_kbh); cudaGetSymbolAddress((void**)&kbl, g_kbl);
    cudaGetSymbolAddress((void**)&vbh, g_vbh); cudaGetSymbolAddress((void**)&vbl, g_vbl);

    cudaFuncSetAttribute(hgemm_split, cudaFuncAttributeMaxDynamicSharedMemorySize, HG_SMEM);
    cudaFuncSetAttribute(attn_mma, cudaFuncAttributeMaxDynamicSharedMemorySize, ATTN_SMEM);

    if (g_s1 == nullptr) {
        cudaStreamCreateWithFlags(&g_s1, cudaStreamNonBlocking);
        cudaEventCreateWithFlags(&g_evFork, cudaEventDisableTiming);
        cudaEventCreateWithFlags(&g_evX,    cudaEventDisableTiming);
        cudaEventCreateWithFlags(&g_evJoin, cudaEventDisableTiming);
        cudaEventCreateWithFlags(&g_evA,    cudaEventDisableTiming);
        cudaEventCreateWithFlags(&g_evDone, cudaEventDisableTiming);
    }

    const int BIG = 1 << 30;
    const int HALF_M = Sc;                  // 2048 rows per batch
    cudaStream_t s0 = 0;
    cudaStream_t s1 = g_s1;

    // ---- fork ----
    cudaEventRecord(g_evFork, s0);
    cudaStreamWaitEvent(s1, g_evFork, 0);

    // Branch A (s0): x split -> Wq transpose -> Q-GEMM -> norm_q
    split_f32<<<(Mc * HID / 4 + 255) / 256, 256, 0, s0>>>(x, xh, xl, Mc * HID / 4);
    cudaEventRecord(g_evX, s0);
    transpose_split<<<dim3(NQ / 32, HID / 32), dim3(32, 8), 0, s0>>>(Wq, wqh, wql, HID, NQ);
    hgemm_split<<<dim3(NQ / 128, Mc / 128), 256, HG_SMEM, s0>>>(
        xh, xl, wqh, wql, qraw_p, wqh, wql, qraw_p, BIG, Mc, NQ, HID);
    norm_rope_q_bf<<<(Mc * Hc) / 8, 256, 0, s0>>>(qraw_p, qn_w, qbh, qbl);
    cudaEventRecord(g_evA, s0);

    // Branch B (s1): Wk/Wv/Wo transposes -> KV-GEMM -> norm_k + v split
    transpose_split<<<dim3(NK / 32, HID / 32), dim3(32, 8), 0, s1>>>(Wk, wkh, wkl, HID, NK);
    transpose_split<<<dim3(NK / 32, HID / 32), dim3(32, 8), 0, s1>>>(Wv, wvh, wvl, HID, NK);
    transpose_split<<<dim3(HID / 32, HID / 32), dim3(32, 8), 0, s1>>>(Wo, woh, wol, HID, HID);
    cudaStreamWaitEvent(s1, g_evX, 0);
    hgemm_split<<<dim3(2 * NK / 128, Mc / 128), 256, HG_SMEM, s1>>>(
        xh, xl, wkh, wkl, k_p, wvh, wvl, v_p, NK / 128, Mc, NK, HID);
    norm_rope_k_bf<<<(Mc * KVc) / 8, 256, 0, s1>>>(k_p, kn_w, kbh, kbl);
    split_f32<<<(Mc * NK / 4 + 255) / 256, 256, 0, s1>>>(v_p, vbh, vbl, Mc * NK / 4);
    cudaEventRecord(g_evJoin, s1);

    // ---- per-batch back half ----
    // s0: batch 0
    cudaStreamWaitEvent(s0, g_evJoin, 0);
    attn_mma<<<dim3(Sc / 128, Hc, 1), 256, ATTN_SMEM, s0>>>(
        qbh, qbl, kbh, kbl, vbh, vbl, qraw_p, z_p);
    split_f32<<<(HALF_M * HID / 4 + 255) / 256, 256, 0, s0>>>(z_p, zh, zl, HALF_M * HID / 4);
    hgemm_split<<<dim3(HID / 128, HALF_M / 128), 256, HG_SMEM, s0>>>(
        zh, zl, woh, wol, out, woh, wol, out, BIG, HALF_M, HID, HID);

    // s1: batch 1 (needs q from s0's branch A)
    cudaStreamWaitEvent(s1, g_evA, 0);
    {
        const size_t oQ = (size_t)Sc * Hc * Dc;
        const size_t oK = (size_t)Sc * NK;
        attn_mma<<<dim3(Sc / 128, Hc, 1), 256, ATTN_SMEM, s1>>>(
            qbh + oQ, qbl + oQ, kbh + oK, kbl + oK, vbh + oK, vbl + oK,
            qraw_p + (size_t)Sc * NQ, z_p + oQ);
        split_f32<<<(HALF_M * HID / 4 + 255) / 256, 256, 0, s1>>>(
            z_p + oQ, zh + oQ, zl + oQ, HALF_M * HID / 4);
        hgemm_split<<<dim3(HID / 128, HALF_M / 128), 256, HG_SMEM, s1>>>(
            zh + oQ, zl + oQ, woh, wol, out + oQ, woh, wol, out + oQ, BIG, HALF_M, HID, HID);
    }
    cudaEventRecord(g_evDone, s1);

    // ---- final join back to capture stream ----
    cudaStreamWaitEvent(s0, g_evDone, 0);
}